// round 9
// baseline (speedup 1.0000x reference)
#include <cuda_runtime.h>
#include <cuda_bf16.h>
#include <math.h>
#include <stdint.h>

// ---------------------------------------------------------------------------
// Problem constants
// ---------------------------------------------------------------------------
#define BATCH 8
#define ICH   256
#define NFC   128
#define NPIX  1024
#define KCONV 4096
#define MROWS 8192

// ---------------------------------------------------------------------------
// Device scratch (bf16 hi/lo split pairs throughout the GEMM chain)
// ---------------------------------------------------------------------------
__device__ __nv_bfloat16 g_w1h[ICH * KCONV], g_w1l[ICH * KCONV];
__device__ __nv_bfloat16 g_wfh[NFC * ICH],  g_wfl[NFC * ICH];
__device__ __nv_bfloat16 g_wsh[NFC * ICH],  g_wsl[NFC * ICH];
__device__ __nv_bfloat16 g_wgh[NFC * ICH],  g_wgl[NFC * ICH];

__device__ __nv_bfloat16 g_xh[MROWS * KCONV], g_xl[MROWS * KCONV];   // im2col(x)
__device__ __nv_bfloat16 g_yh[MROWS * ICH],  g_yl[MROWS * ICH];
__device__ __nv_bfloat16 g_faih[BATCH * NPIX * NFC], g_fail_[BATCH * NPIX * NFC];
__device__ __nv_bfloat16 g_sith[BATCH * NPIX * NFC], g_sitl[BATCH * NPIX * NFC];
__device__ __nv_bfloat16 g_gTh[BATCH * NFC * NPIX],  g_gTl[BATCH * NFC * NPIX];  // [b][c][m]
__device__ __nv_bfloat16 g_Sh[BATCH * NPIX * NPIX],  g_Sl[BATCH * NPIX * NPIX];  // [b][n][m]
__device__ float g_attp[4][BATCH * NPIX * NFC];   // split-K partials

// ---------------------------------------------------------------------------
// Portable helpers (base sm_103)
// ---------------------------------------------------------------------------
__device__ __forceinline__ uint32_t smem_u32(const void* p) {
    uint32_t a;
    asm("{ .reg .u64 t; cvta.to.shared.u64 t, %1; cvt.u32.u64 %0, t; }" : "=r"(a) : "l"(p));
    return a;
}

__device__ __forceinline__ void cp16(uint32_t saddr, const void* gaddr) {
    asm volatile("cp.async.cg.shared.global [%0], [%1], 16;" :: "r"(saddr), "l"(gaddr));
}
#define CP_COMMIT() asm volatile("cp.async.commit_group;" ::: "memory")
#define CP_WAIT(n)  asm volatile("cp.async.wait_group %0;" :: "n"(n) : "memory")

__device__ __forceinline__ void ldsm_x4(uint32_t& r0, uint32_t& r1, uint32_t& r2, uint32_t& r3,
                                        uint32_t addr) {
    asm volatile("ldmatrix.sync.aligned.m8n8.x4.shared.b16 {%0,%1,%2,%3}, [%4];"
        : "=r"(r0), "=r"(r1), "=r"(r2), "=r"(r3) : "r"(addr));
}

__device__ __forceinline__ void mma_bf16(float* c, const uint32_t* a,
                                         uint32_t b0, uint32_t b1) {
    asm volatile(
        "mma.sync.aligned.m16n8k16.row.col.f32.bf16.bf16.f32 "
        "{%0,%1,%2,%3}, {%4,%5,%6,%7}, {%8,%9}, {%0,%1,%2,%3};"
        : "+f"(c[0]), "+f"(c[1]), "+f"(c[2]), "+f"(c[3])
        : "r"(a[0]), "r"(a[1]), "r"(a[2]), "r"(a[3]), "r"(b0), "r"(b1));
}

__device__ __forceinline__ void split2(float a, float b, uint32_t& ph, uint32_t& pl) {
    __nv_bfloat16 h0 = __float2bfloat16_rn(a), h1 = __float2bfloat16_rn(b);
    float ra = a - __bfloat162float(h0), rb = b - __bfloat162float(h1);
    __nv_bfloat16 l0 = __float2bfloat16_rn(ra), l1 = __float2bfloat16_rn(rb);
    ph = (uint32_t)__bfloat16_as_ushort(h0) | ((uint32_t)__bfloat16_as_ushort(h1) << 16);
    pl = (uint32_t)__bfloat16_as_ushort(l0) | ((uint32_t)__bfloat16_as_ushort(l1) << 16);
}

// ---------------------------------------------------------------------------
// Unified 128x128 GEMM tile, cp.async double-buffered (R6 ordering)
//   smem per stage: Ahi/Alo/Bhi/Blo each 128 rows x 32 bf16, stride 80B
//   warp tile 32x64 (4 warps M x 2 warps N), B loaded per np-half
// ---------------------------------------------------------------------------
#define RSTRIDE 80
#define MAT      10240
#define STG      40960
#define GEMM_SMEM (2 * STG)     // 81920

__device__ __forceinline__ void gemm_tile_128x128(
    const __nv_bfloat16* __restrict__ Ah, const __nv_bfloat16* __restrict__ Al, int lda,
    const __nv_bfloat16* __restrict__ Bh, const __nv_bfloat16* __restrict__ Bl, int ldb,
    int K, uint32_t sbase, float acc[2][8][4])
{
    const int tid = threadIdx.x;
    const int l = tid & 31;
    const int wid = tid >> 5;
    const int warp_m = wid & 3, warp_n = wid >> 2;
    const int row = tid >> 1;       // 0..127
    const int c2  = (tid & 1) * 2;  // chunk base (of 4 16B chunks per row)

    const uint32_t a_row = (uint32_t)(warp_m * 32 + (l & 15));
    const uint32_t a_co  = (uint32_t)((l >> 4) << 4);
    const uint32_t b_row = (uint32_t)(warp_n * 64 + (l & 7) + ((l >> 4) & 1) * 8);
    const uint32_t b_co  = (uint32_t)(((l >> 3) & 1) << 4);

    auto issue = [&](int s, int kb) {
        const uint32_t st = sbase + (uint32_t)s * STG;
        #pragma unroll
        for (int j = 0; j < 2; ++j) {
            const int ch = c2 + j;
            const uint32_t so = st + (uint32_t)(row * RSTRIDE + ch * 16);
            const size_t go = (size_t)row * lda + kb + ch * 8;
            cp16(so,            Ah + go);
            cp16(so + MAT,      Al + go);
            const size_t gb = (size_t)row * ldb + kb + ch * 8;
            cp16(so + 2 * MAT,  Bh + gb);
            cp16(so + 3 * MAT,  Bl + gb);
        }
    };

    const int KT = K >> 5;
    issue(0, 0);
    CP_COMMIT();

    for (int kt = 0; kt < KT; ++kt) {
        if (kt + 1 < KT) {
            issue((kt + 1) & 1, (kt + 1) << 5);
            CP_COMMIT();
            CP_WAIT(1);
        } else {
            CP_WAIT(0);
        }
        __syncthreads();

        const uint32_t st = sbase + (uint32_t)((kt & 1) * STG);
        #pragma unroll
        for (int ks = 0; ks < 2; ++ks) {
            uint32_t ah[2][4], al[2][4];
            #pragma unroll
            for (int bm = 0; bm < 2; ++bm) {
                const uint32_t aaddr = st + (a_row + bm * 16) * RSTRIDE + ks * 32 + a_co;
                ldsm_x4(ah[bm][0], ah[bm][1], ah[bm][2], ah[bm][3], aaddr);
                ldsm_x4(al[bm][0], al[bm][1], al[bm][2], al[bm][3], aaddr + MAT);
            }
            #pragma unroll
            for (int nh = 0; nh < 2; ++nh) {
                uint32_t bh[2][4], bl[2][4];
                #pragma unroll
                for (int np2 = 0; np2 < 2; ++np2) {
                    const int np = nh * 2 + np2;
                    const uint32_t baddr = st + 2 * MAT + (b_row + np * 16) * RSTRIDE + ks * 32 + b_co;
                    ldsm_x4(bh[np2][0], bh[np2][1], bh[np2][2], bh[np2][3], baddr);
                    ldsm_x4(bl[np2][0], bl[np2][1], bl[np2][2], bl[np2][3], baddr + MAT);
                }
                // variant-major, dep distance 8
                #pragma unroll
                for (int np2 = 0; np2 < 2; ++np2)
                    #pragma unroll
                    for (int bm = 0; bm < 2; ++bm) {
                        const int np = nh * 2 + np2;
                        mma_bf16(acc[bm][np * 2],     ah[bm], bh[np2][0], bh[np2][1]);
                        mma_bf16(acc[bm][np * 2 + 1], ah[bm], bh[np2][2], bh[np2][3]);
                    }
                #pragma unroll
                for (int np2 = 0; np2 < 2; ++np2)
                    #pragma unroll
                    for (int bm = 0; bm < 2; ++bm) {
                        const int np = nh * 2 + np2;
                        mma_bf16(acc[bm][np * 2],     al[bm], bh[np2][0], bh[np2][1]);
                        mma_bf16(acc[bm][np * 2 + 1], al[bm], bh[np2][2], bh[np2][3]);
                    }
                #pragma unroll
                for (int np2 = 0; np2 < 2; ++np2)
                    #pragma unroll
                    for (int bm = 0; bm < 2; ++bm) {
                        const int np = nh * 2 + np2;
                        mma_bf16(acc[bm][np * 2],     ah[bm], bl[np2][0], bl[np2][1]);
                        mma_bf16(acc[bm][np * 2 + 1], ah[bm], bl[np2][2], bl[np2][3]);
                    }
            }
        }
        __syncthreads();
    }
}

// ---------------------------------------------------------------------------
// Kernel 0a: weight preconversion
// ---------------------------------------------------------------------------
__global__ __launch_bounds__(256)
void prep_kernel(const float* __restrict__ w1, const float* __restrict__ wf,
                 const float* __restrict__ ws, const float* __restrict__ wg)
{
    const int idx = blockIdx.x * 256 + threadIdx.x;
    const int NW1 = ICH * KCONV;
    if (idx < NW1) {
        float v = w1[idx];
        __nv_bfloat16 h = __float2bfloat16_rn(v);
        g_w1h[idx] = h;
        g_w1l[idx] = __float2bfloat16_rn(v - __bfloat162float(h));
    } else {
        int j = idx - NW1;
        if (j >= 3 * NFC * ICH) return;
        const int which = j >> 15;
        const int e = j & 32767;
        float v = (which == 0 ? wf : which == 1 ? ws : wg)[e];
        __nv_bfloat16 h = __float2bfloat16_rn(v);
        __nv_bfloat16 l = __float2bfloat16_rn(v - __bfloat162float(h));
        if (which == 0)      { g_wfh[e] = h; g_wfl[e] = l; }
        else if (which == 1) { g_wsh[e] = h; g_wsl[e] = l; }
        else                 { g_wgh[e] = h; g_wgl[e] = l; }
    }
}

// ---------------------------------------------------------------------------
// Kernel 0b: im2col of x into bf16 hi/lo
// ---------------------------------------------------------------------------
#define I2C_RS 264
#define I2C_SMEM (2 * 64 * I2C_RS * 2)

__global__ __launch_bounds__(256, 1)
void im2col_kernel(const float* __restrict__ x)
{
    extern __shared__ char smraw[];
    __nv_bfloat16* sh = (__nv_bfloat16*)smraw;
    __nv_bfloat16* sl = (__nv_bfloat16*)(smraw + 64 * I2C_RS * 2);

    const int bx = blockIdx.x;
    const int icc = bx & 7;
    const int oh  = (bx >> 3) & 31;
    const int b   = bx >> 8;
    const int t = threadIdx.x;

    #pragma unroll
    for (int it = 0; it < 16; ++it) {
        const int f = t + it * 256;
        const int w4 = f & 63;
        const int kh = (f >> 6) & 7;
        const int i  = f >> 9;
        const float4 v = *(const float4*)&x[((size_t)(b * 64 + icc * 8 + i) * 256 + oh * 8 + kh) * 256 + w4 * 4];
        const int row = i * 8 + kh;
        __nv_bfloat16 h0 = __float2bfloat16_rn(v.x), h1 = __float2bfloat16_rn(v.y);
        __nv_bfloat16 h2 = __float2bfloat16_rn(v.z), h3 = __float2bfloat16_rn(v.w);
        sh[row * I2C_RS + w4 * 4 + 0] = h0;
        sh[row * I2C_RS + w4 * 4 + 1] = h1;
        sh[row * I2C_RS + w4 * 4 + 2] = h2;
        sh[row * I2C_RS + w4 * 4 + 3] = h3;
        sl[row * I2C_RS + w4 * 4 + 0] = __float2bfloat16_rn(v.x - __bfloat162float(h0));
        sl[row * I2C_RS + w4 * 4 + 1] = __float2bfloat16_rn(v.y - __bfloat162float(h1));
        sl[row * I2C_RS + w4 * 4 + 2] = __float2bfloat16_rn(v.z - __bfloat162float(h2));
        sl[row * I2C_RS + w4 * 4 + 3] = __float2bfloat16_rn(v.w - __bfloat162float(h3));
    }
    __syncthreads();

    #pragma unroll
    for (int it = 0; it < 8; ++it) {
        const int f = t + it * 256;
        const int kh = f & 7;
        const int i  = (f >> 3) & 7;
        const int ow = f >> 6;
        const int row = i * 8 + kh;
        const size_t r = (size_t)b * 1024 + oh * 32 + ow;
        const size_t kbase = (size_t)(icc * 8 + i) * 64 + kh * 8;
        *(uint4*)&g_xh[r * KCONV + kbase] = *(const uint4*)&sh[row * I2C_RS + ow * 8];
        *(uint4*)&g_xl[r * KCONV + kbase] = *(const uint4*)&sl[row * I2C_RS + ow * 8];
    }
}

// ---------------------------------------------------------------------------
// Kernel 1: conv1 GEMM (M=8192, N=256, K=4096); grid (64 m, 2 n)
// ---------------------------------------------------------------------------
__global__ __launch_bounds__(256, 2)
void conv1_mma_kernel(const float* __restrict__ bnS, const float* __restrict__ bnB)
{
    extern __shared__ char smem[];
    const uint32_t sbase = smem_u32(smem);

    const int m0 = blockIdx.x * 128;
    const int n0 = blockIdx.y * 128;

    float acc[2][8][4] = {};
    gemm_tile_128x128(g_xh + (size_t)m0 * KCONV, g_xl + (size_t)m0 * KCONV, KCONV,
                      g_w1h + (size_t)n0 * KCONV, g_w1l + (size_t)n0 * KCONV, KCONV,
                      KCONV, sbase, acc);

    const int wid = threadIdx.x >> 5, l = threadIdx.x & 31;
    const int erow0 = m0 + (wid & 3) * 32 + (l >> 2);
    const int ecol0 = n0 + (wid >> 2) * 64 + (l & 3) * 2;
    #pragma unroll
    for (int bm = 0; bm < 2; ++bm) {
        #pragma unroll
        for (int nb = 0; nb < 8; ++nb) {
            const int col = ecol0 + nb * 8;
            const float s0 = bnS[col], s1 = bnS[col + 1];
            const float v0 = bnB[col], v1 = bnB[col + 1];
            const int r0 = erow0 + bm * 16;
            float a0 = fmaxf(acc[bm][nb][0] * s0 + v0, 0.0f);
            float a1 = fmaxf(acc[bm][nb][1] * s1 + v1, 0.0f);
            float a2 = fmaxf(acc[bm][nb][2] * s0 + v0, 0.0f);
            float a3 = fmaxf(acc[bm][nb][3] * s1 + v1, 0.0f);
            uint32_t ph, pl;
            split2(a0, a1, ph, pl);
            *(uint32_t*)&g_yh[(size_t)r0 * ICH + col] = ph;
            *(uint32_t*)&g_yl[(size_t)r0 * ICH + col] = pl;
            split2(a2, a3, ph, pl);
            *(uint32_t*)&g_yh[(size_t)(r0 + 8) * ICH + col] = ph;
            *(uint32_t*)&g_yl[(size_t)(r0 + 8) * ICH + col] = pl;
        }
    }
}

// ---------------------------------------------------------------------------
// Kernel 2: projections (M=8192, N=128, K=256); grid (64 m, 1, 3)
// ---------------------------------------------------------------------------
__global__ __launch_bounds__(256, 2)
void proj_mma_kernel(const float* __restrict__ sf, const float* __restrict__ bf,
                     const float* __restrict__ ss, const float* __restrict__ bs,
                     const float* __restrict__ sg, const float* __restrict__ bg)
{
    extern __shared__ char smem[];
    const uint32_t sbase = smem_u32(smem);

    const int z = blockIdx.z;
    const __nv_bfloat16* Wh = (z == 0) ? g_wfh : (z == 1) ? g_wsh : g_wgh;
    const __nv_bfloat16* Wl = (z == 0) ? g_wfl : (z == 1) ? g_wsl : g_wgl;
    const float* Sv = (z == 0) ? sf : (z == 1) ? ss : sg;
    const float* Bv = (z == 0) ? bf : (z == 1) ? bs : bg;

    const int m0 = blockIdx.x * 128;

    float acc[2][8][4] = {};
    gemm_tile_128x128(g_yh + (size_t)m0 * ICH, g_yl + (size_t)m0 * ICH, ICH,
                      Wh, Wl, ICH, ICH, sbase, acc);

    const int wid = threadIdx.x >> 5, l = threadIdx.x & 31;
    const int erow0 = m0 + (wid & 3) * 32 + (l >> 2);
    const int ecol0 = (wid >> 2) * 64 + (l & 3) * 2;
    #pragma unroll
    for (int bm = 0; bm < 2; ++bm) {
        #pragma unroll
        for (int nb = 0; nb < 8; ++nb) {
            const int col = ecol0 + nb * 8;
            const float s0 = Sv[col], s1 = Sv[col + 1];
            const float v0 = Bv[col], v1 = Bv[col + 1];
            const int r0 = erow0 + bm * 16;
            float a0 = fmaxf(acc[bm][nb][0] * s0 + v0, 0.0f);
            float a1 = fmaxf(acc[bm][nb][1] * s1 + v1, 0.0f);
            float a2 = fmaxf(acc[bm][nb][2] * s0 + v0, 0.0f);
            float a3 = fmaxf(acc[bm][nb][3] * s1 + v1, 0.0f);
            if (z < 2) {
                __nv_bfloat16* Oh = (z == 0) ? g_faih : g_sith;
                __nv_bfloat16* Ol = (z == 0) ? g_fail_ : g_sitl;
                uint32_t ph, pl;
                split2(a0, a1, ph, pl);
                *(uint32_t*)&Oh[(size_t)r0 * NFC + col] = ph;
                *(uint32_t*)&Ol[(size_t)r0 * NFC + col] = pl;
                split2(a2, a3, ph, pl);
                *(uint32_t*)&Oh[(size_t)(r0 + 8) * NFC + col] = ph;
                *(uint32_t*)&Ol[(size_t)(r0 + 8) * NFC + col] = pl;
            } else {
                const int bb = r0 >> 10;
                const int n  = r0 & 1023;
                const size_t base = (size_t)bb * NFC * NPIX;
                float vals[4] = {a0, a1, a2, a3};
                #pragma unroll
                for (int ii = 0; ii < 4; ii++) {
                    const int cc = col + (ii & 1);
                    const int rr = n + (ii >> 1) * 8;
                    __nv_bfloat16 h = __float2bfloat16_rn(vals[ii]);
                    g_gTh[base + (size_t)cc * NPIX + rr] = h;
                    g_gTl[base + (size_t)cc * NPIX + rr] =
                        __float2bfloat16_rn(vals[ii] - __bfloat162float(h));
                }
            }
        }
    }
}

// ---------------------------------------------------------------------------
// Kernel 3: score S = sigmoid(fai . sit); grid (8 m, 8 n, 8 b)
// ---------------------------------------------------------------------------
__global__ __launch_bounds__(256, 2)
void score_mma_kernel()
{
    extern __shared__ char smem[];
    const uint32_t sbase = smem_u32(smem);

    const int b  = blockIdx.z;
    const int m0 = blockIdx.x * 128;
    const int n0 = blockIdx.y * 128;
    const size_t abase = (size_t)b * NPIX * NFC;

    float acc[2][8][4] = {};
    gemm_tile_128x128(g_faih + abase + (size_t)m0 * NFC, g_fail_ + abase + (size_t)m0 * NFC, NFC,
                      g_sith + abase + (size_t)n0 * NFC, g_sitl + abase + (size_t)n0 * NFC, NFC,
                      NFC, sbase, acc);

    const size_t sb_out = (size_t)b * NPIX * NPIX;
    const int wid = threadIdx.x >> 5, l = threadIdx.x & 31;
    const int erow0 = m0 + (wid & 3) * 32 + (l >> 2);
    const int ecol0 = n0 + (wid >> 2) * 64 + (l & 3) * 2;
    #pragma unroll
    for (int bm = 0; bm < 2; ++bm) {
        #pragma unroll
        for (int nb = 0; nb < 8; ++nb) {
            const int col = ecol0 + nb * 8;
            const int r0 = erow0 + bm * 16;
            float a0 = 1.0f / (1.0f + expf(-acc[bm][nb][0]));
            float a1 = 1.0f / (1.0f + expf(-acc[bm][nb][1]));
            float a2 = 1.0f / (1.0f + expf(-acc[bm][nb][2]));
            float a3 = 1.0f / (1.0f + expf(-acc[bm][nb][3]));
            uint32_t ph, pl;
            split2(a0, a1, ph, pl);
            *(uint32_t*)&g_Sh[sb_out + (size_t)r0 * NPIX + col] = ph;
            *(uint32_t*)&g_Sl[sb_out + (size_t)r0 * NPIX + col] = pl;
            split2(a2, a3, ph, pl);
            *(uint32_t*)&g_Sh[sb_out + (size_t)(r0 + 8) * NPIX + col] = ph;
            *(uint32_t*)&g_Sl[sb_out + (size_t)(r0 + 8) * NPIX + col] = pl;
        }
    }
}

// ---------------------------------------------------------------------------
// Kernel 4: att = S @ gamaT, split-K(4); grid (8 m, 1, 32)
// ---------------------------------------------------------------------------
__global__ __launch_bounds__(256, 2)
void attn_mma_kernel()
{
    extern __shared__ char smem[];
    const uint32_t sbase = smem_u32(smem);

    const int z  = blockIdx.z;
    const int b  = z >> 2;
    const int ks = z & 3;
    const int m0 = blockIdx.x * 128;
    const size_t sBase = (size_t)b * NPIX * NPIX;
    const size_t gBase = (size_t)b * NFC * NPIX;
    const int kofs = ks * 256;

    float acc[2][8][4] = {};
    gemm_tile_128x128(g_Sh + sBase + (size_t)m0 * NPIX + kofs,
                      g_Sl + sBase + (size_t)m0 * NPIX + kofs, NPIX,
                      g_gTh + gBase + kofs,
                      g_gTl + gBase + kofs, NPIX,
                      256, sbase, acc);

    float* outp = g_attp[ks];
    const int wid = threadIdx.x >> 5, l = threadIdx.x & 31;
    const int erow0 = m0 + (wid & 3) * 32 + (l >> 2);
    const int ecol0 = (wid >> 2) * 64 + (l & 3) * 2;
    #pragma unroll
    for (int bm = 0; bm < 2; ++bm) {
        #pragma unroll
        for (int nb = 0; nb < 8; ++nb) {
            const int col = ecol0 + nb * 8;
            const int r0 = erow0 + bm * 16;
            float2 o0 = {acc[bm][nb][0], acc[bm][nb][1]};
            float2 o1 = {acc[bm][nb][2], acc[bm][nb][3]};
            *(float2*)&outp[((size_t)b * NPIX + r0) * NFC + col] = o0;
            *(float2*)&outp[((size_t)b * NPIX + r0 + 8) * NFC + col] = o1;
        }
    }
}

// ---------------------------------------------------------------------------
// Kernel 5: bilinear upsample x8 (align_corners), sums split-K partials
// ---------------------------------------------------------------------------
__global__ __launch_bounds__(256)
void upsample_kernel(float* __restrict__ out)
{
    __shared__ float rows[3][32];
    const int gx = blockIdx.x;
    const int yt = gx & 31;
    const int c  = (gx >> 5) & 127;
    const int b  = gx >> 12;
    const int t = threadIdx.x;

    const float sc = 31.0f / 255.0f;
    const int rbase = (int)floorf((float)(yt * 8) * sc);
    if (t < 96) {
        const int rr = t >> 5, xx = t & 31;
        const int r = min(rbase + rr, 31);
        const size_t idx = ((size_t)b * NPIX + r * 32 + xx) * NFC + c;
        rows[rr][xx] = g_attp[0][idx] + g_attp[1][idx] + g_attp[2][idx] + g_attp[3][idx];
    }
    __syncthreads();

    const int xo = t;
    const float xs = (float)xo * sc;
    const int x0 = (int)floorf(xs);
    const float wx = xs - (float)x0;
    const int x1 = min(x0 + 1, 31);
    const size_t obase = ((size_t)(b * 128 + c)) * 256 * 256;

    #pragma unroll
    for (int i = 0; i < 8; ++i) {
        const int yo = yt * 8 + i;
        const float ysf = (float)yo * sc;
        const int y0 = (int)floorf(ysf);
        const float wy = ysf - (float)y0;
        const int y1 = min(y0 + 1, 31);
        const int r0 = y0 - rbase, r1 = y1 - rbase;
        const float v00 = rows[r0][x0], v01 = rows[r0][x1];
        const float v10 = rows[r1][x0], v11 = rows[r1][x1];
        const float top0 = v00 * (1.0f - wy) + v10 * wy;
        const float top1 = v01 * (1.0f - wy) + v11 * wy;
        out[obase + (size_t)yo * 256 + xo] = top0 * (1.0f - wx) + top1 * wx;
    }
}

// ---------------------------------------------------------------------------
// Launch
// ---------------------------------------------------------------------------
extern "C" void kernel_launch(void* const* d_in, const int* in_sizes, int n_in,
                              void* d_out, int out_size)
{
    const float* x     = (const float*)d_in[0];
    const float* w1    = (const float*)d_in[1];
    const float* bn1_s = (const float*)d_in[2];
    const float* bn1_b = (const float*)d_in[3];
    const float* w_fai = (const float*)d_in[4];
    const float* bnf_s = (const float*)d_in[5];
    const float* bnf_b = (const float*)d_in[6];
    const float* w_sit = (const float*)d_in[7];
    const float* bns_s = (const float*)d_in[8];
    const float* bns_b = (const float*)d_in[9];
    const float* w_gam = (const float*)d_in[10];
    const float* bng_s = (const float*)d_in[11];
    const float* bng_b = (const float*)d_in[12];
    float* out = (float*)d_out;

    static bool attr_done = false;
    if (!attr_done) {
        cudaFuncSetAttribute(conv1_mma_kernel, cudaFuncAttributeMaxDynamicSharedMemorySize, GEMM_SMEM);
        cudaFuncSetAttribute(proj_mma_kernel,  cudaFuncAttributeMaxDynamicSharedMemorySize, GEMM_SMEM);
        cudaFuncSetAttribute(score_mma_kernel, cudaFuncAttributeMaxDynamicSharedMemorySize, GEMM_SMEM);
        cudaFuncSetAttribute(attn_mma_kernel,  cudaFuncAttributeMaxDynamicSharedMemorySize, GEMM_SMEM);
        cudaFuncSetAttribute(im2col_kernel,    cudaFuncAttributeMaxDynamicSharedMemorySize, I2C_SMEM);
        attr_done = true;
    }

    // 0a. weight preconversion
    {
        const int total = ICH * KCONV + 3 * NFC * ICH;
        prep_kernel<<<(total + 255) / 256, 256>>>(w1, w_fai, w_sit, w_gam);
    }
    // 0b. im2col(x) -> bf16 hi/lo
    im2col_kernel<<<2048, 256, I2C_SMEM>>>(x);
    // 1. conv1 GEMM + BN + ReLU
    {
        dim3 grid(MROWS / 128, ICH / 128);
        conv1_mma_kernel<<<grid, 256, GEMM_SMEM>>>(bn1_s, bn1_b);
    }
    // 2. projections
    {
        dim3 grid(MROWS / 128, 1, 3);
        proj_mma_kernel<<<grid, 256, GEMM_SMEM>>>(bnf_s, bnf_b, bns_s, bns_b, bng_s, bng_b);
    }
    // 3. S = sigmoid(fai . sit)
    {
        dim3 grid(NPIX / 128, NPIX / 128, BATCH);
        score_mma_kernel<<<grid, 256, GEMM_SMEM>>>();
    }
    // 4. att = S @ gamaT (split-K 4)
    {
        dim3 grid(NPIX / 128, 1, BATCH * 4);
        attn_mma_kernel<<<grid, 256, GEMM_SMEM>>>();
    }
    // 5. upsample (+ split-K reduce)
    upsample_kernel<<<BATCH * 128 * 32, 256>>>(out);
}

// round 10
// speedup vs baseline: 1.1924x; 1.1924x over previous
#include <cuda_runtime.h>
#include <cuda_bf16.h>
#include <math.h>
#include <stdint.h>

// ---------------------------------------------------------------------------
// Problem constants
// ---------------------------------------------------------------------------
#define BATCH 8
#define ICH   256
#define NFC   128
#define NPIX  1024
#define KCONV 4096
#define MROWS 8192

// ---------------------------------------------------------------------------
// Device scratch
// ---------------------------------------------------------------------------
__device__ __nv_bfloat16 g_w1h[ICH * KCONV], g_w1l[ICH * KCONV];
__device__ __nv_bfloat16 g_wfh[NFC * ICH],  g_wfl[NFC * ICH];
__device__ __nv_bfloat16 g_wsh[NFC * ICH],  g_wsl[NFC * ICH];
__device__ __nv_bfloat16 g_wgh[NFC * ICH],  g_wgl[NFC * ICH];

__device__ __nv_bfloat16 g_xh[MROWS * KCONV], g_xl[MROWS * KCONV];   // im2col(x)
__device__ __nv_bfloat16 g_yh[MROWS * ICH],  g_yl[MROWS * ICH];
__device__ __nv_bfloat16 g_faih[BATCH * NPIX * NFC];                 // bf16 only
__device__ __nv_bfloat16 g_sith[BATCH * NPIX * NFC];
__device__ __nv_bfloat16 g_gTh[BATCH * NFC * NPIX];                  // [b][c][m]
__device__ __nv_bfloat16 g_Sh[BATCH * NPIX * NPIX];                  // [b][n][m]
__device__ float g_att0[BATCH * NPIX * NFC];   // split-K partials
__device__ float g_att1[BATCH * NPIX * NFC];

// ---------------------------------------------------------------------------
// Portable helpers (base sm_103)
// ---------------------------------------------------------------------------
__device__ __forceinline__ uint32_t smem_u32(const void* p) {
    uint32_t a;
    asm("{ .reg .u64 t; cvta.to.shared.u64 t, %1; cvt.u32.u64 %0, t; }" : "=r"(a) : "l"(p));
    return a;
}

__device__ __forceinline__ void cp16(uint32_t saddr, const void* gaddr) {
    asm volatile("cp.async.cg.shared.global [%0], [%1], 16;" :: "r"(saddr), "l"(gaddr));
}
#define CP_COMMIT() asm volatile("cp.async.commit_group;" ::: "memory")
#define CP_WAIT(n)  asm volatile("cp.async.wait_group %0;" :: "n"(n) : "memory")

__device__ __forceinline__ void ldsm_x4(uint32_t& r0, uint32_t& r1, uint32_t& r2, uint32_t& r3,
                                        uint32_t addr) {
    asm volatile("ldmatrix.sync.aligned.m8n8.x4.shared.b16 {%0,%1,%2,%3}, [%4];"
        : "=r"(r0), "=r"(r1), "=r"(r2), "=r"(r3) : "r"(addr));
}

__device__ __forceinline__ void mma_bf16(float* c, const uint32_t* a,
                                         uint32_t b0, uint32_t b1) {
    asm volatile(
        "mma.sync.aligned.m16n8k16.row.col.f32.bf16.bf16.f32 "
        "{%0,%1,%2,%3}, {%4,%5,%6,%7}, {%8,%9}, {%0,%1,%2,%3};"
        : "+f"(c[0]), "+f"(c[1]), "+f"(c[2]), "+f"(c[3])
        : "r"(a[0]), "r"(a[1]), "r"(a[2]), "r"(a[3]), "r"(b0), "r"(b1));
}

__device__ __forceinline__ void split2(float a, float b, uint32_t& ph, uint32_t& pl) {
    __nv_bfloat16 h0 = __float2bfloat16_rn(a), h1 = __float2bfloat16_rn(b);
    float ra = a - __bfloat162float(h0), rb = b - __bfloat162float(h1);
    __nv_bfloat16 l0 = __float2bfloat16_rn(ra), l1 = __float2bfloat16_rn(rb);
    ph = (uint32_t)__bfloat16_as_ushort(h0) | ((uint32_t)__bfloat16_as_ushort(h1) << 16);
    pl = (uint32_t)__bfloat16_as_ushort(l0) | ((uint32_t)__bfloat16_as_ushort(l1) << 16);
}

__device__ __forceinline__ uint32_t packbf2(float a, float b) {
    __nv_bfloat16 h0 = __float2bfloat16_rn(a), h1 = __float2bfloat16_rn(b);
    return (uint32_t)__bfloat16_as_ushort(h0) | ((uint32_t)__bfloat16_as_ushort(h1) << 16);
}

// ---------------------------------------------------------------------------
// Split-precision 128x64 GEMM tile (R6 exact: 2-stage, issue->wait->sync)
// ---------------------------------------------------------------------------
#define RSTRIDE 80
#define A_LO_OFF 10240
#define B_HI_OFF 20480
#define B_LO_OFF 25600
#define STG      30720
#define GEMM_SMEM2 (2 * STG)     // 61440

__device__ __forceinline__ void gemm_tile_128x64(
    const __nv_bfloat16* __restrict__ Ah, const __nv_bfloat16* __restrict__ Al, int lda,
    const __nv_bfloat16* __restrict__ Bh, const __nv_bfloat16* __restrict__ Bl, int ldb,
    int K, uint32_t sbase, float acc[2][4][4])
{
    const int tid = threadIdx.x;
    const int l = tid & 31;
    const int wid = tid >> 5;
    const int warp_m = wid & 3, warp_n = wid >> 2;
    const int arow = tid >> 2;
    const int q4   = tid & 3;

    const uint32_t a_row = (uint32_t)(warp_m * 32 + (l & 15));
    const uint32_t a_co  = (uint32_t)((l >> 4) << 4);
    const uint32_t b_row = (uint32_t)(warp_n * 32 + (l & 7) + ((l >> 4) & 1) * 8);
    const uint32_t b_co  = (uint32_t)(((l >> 3) & 1) << 4);

    auto issue = [&](int s, int kb) {
        const uint32_t st = sbase + (uint32_t)s * STG;
        #pragma unroll
        for (int j = 0; j < 2; ++j) {
            const int row = arow + j * 64;
            const uint32_t so = st + (uint32_t)(row * RSTRIDE + q4 * 16);
            cp16(so,            Ah + (size_t)row * lda + kb + q4 * 8);
            cp16(so + A_LO_OFF, Al + (size_t)row * lda + kb + q4 * 8);
        }
        const uint32_t so = st + B_HI_OFF + (uint32_t)(arow * RSTRIDE + q4 * 16);
        cp16(so,                         Bh + (size_t)arow * ldb + kb + q4 * 8);
        cp16(so + (B_LO_OFF - B_HI_OFF), Bl + (size_t)arow * ldb + kb + q4 * 8);
    };

    issue(0, 0);
    CP_COMMIT();

    const int KT = K >> 5;
    for (int kt = 0; kt < KT; ++kt) {
        if (kt + 1 < KT) {
            issue((kt + 1) & 1, (kt + 1) << 5);
            CP_COMMIT();
            CP_WAIT(1);
        } else {
            CP_WAIT(0);
        }
        __syncthreads();

        const uint32_t st = sbase + (uint32_t)((kt & 1) * STG);
        #pragma unroll
        for (int ks = 0; ks < 2; ++ks) {
            uint32_t ah[2][4], al[2][4], bh[2][4], bl[2][4];
            #pragma unroll
            for (int bm = 0; bm < 2; ++bm) {
                const uint32_t aaddr = st + (a_row + bm * 16) * RSTRIDE + ks * 32 + a_co;
                ldsm_x4(ah[bm][0], ah[bm][1], ah[bm][2], ah[bm][3], aaddr);
                ldsm_x4(al[bm][0], al[bm][1], al[bm][2], al[bm][3], aaddr + A_LO_OFF);
            }
            #pragma unroll
            for (int np = 0; np < 2; ++np) {
                const uint32_t baddr = st + B_HI_OFF + (b_row + np * 16) * RSTRIDE + ks * 32 + b_co;
                ldsm_x4(bh[np][0], bh[np][1], bh[np][2], bh[np][3], baddr);
                ldsm_x4(bl[np][0], bl[np][1], bl[np][2], bl[np][3], baddr + (B_LO_OFF - B_HI_OFF));
            }
            #pragma unroll
            for (int np = 0; np < 2; ++np)
                #pragma unroll
                for (int bm = 0; bm < 2; ++bm) {
                    mma_bf16(acc[bm][np * 2],     ah[bm], bh[np][0], bh[np][1]);
                    mma_bf16(acc[bm][np * 2 + 1], ah[bm], bh[np][2], bh[np][3]);
                }
            #pragma unroll
            for (int np = 0; np < 2; ++np)
                #pragma unroll
                for (int bm = 0; bm < 2; ++bm) {
                    mma_bf16(acc[bm][np * 2],     al[bm], bh[np][0], bh[np][1]);
                    mma_bf16(acc[bm][np * 2 + 1], al[bm], bh[np][2], bh[np][3]);
                }
            #pragma unroll
            for (int np = 0; np < 2; ++np)
                #pragma unroll
                for (int bm = 0; bm < 2; ++bm) {
                    mma_bf16(acc[bm][np * 2],     ah[bm], bl[np][0], bl[np][1]);
                    mma_bf16(acc[bm][np * 2 + 1], ah[bm], bl[np][2], bl[np][3]);
                }
        }
        __syncthreads();
    }
}

// ---------------------------------------------------------------------------
// Pure-bf16 128x64 GEMM tile (1 product) — for positive-operand GEMMs
//   smem per stage: A[128x32] + B[64x32], stride 80B -> 15360 B
// ---------------------------------------------------------------------------
#define BB_B_OFF 10240
#define BSTG     15360
#define GEMM_SMEM_B16 (2 * BSTG)   // 30720

__device__ __forceinline__ void gemm_tile_128x64_b16(
    const __nv_bfloat16* __restrict__ A, int lda,
    const __nv_bfloat16* __restrict__ B, int ldb,
    int K, uint32_t sbase, float acc[2][4][4])
{
    const int tid = threadIdx.x;
    const int l = tid & 31;
    const int wid = tid >> 5;
    const int warp_m = wid & 3, warp_n = wid >> 2;
    const int arow = tid >> 2;
    const int q4   = tid & 3;

    const uint32_t a_row = (uint32_t)(warp_m * 32 + (l & 15));
    const uint32_t a_co  = (uint32_t)((l >> 4) << 4);
    const uint32_t b_row = (uint32_t)(warp_n * 32 + (l & 7) + ((l >> 4) & 1) * 8);
    const uint32_t b_co  = (uint32_t)(((l >> 3) & 1) << 4);

    auto issue = [&](int s, int kb) {
        const uint32_t st = sbase + (uint32_t)s * BSTG;
        #pragma unroll
        for (int j = 0; j < 2; ++j) {
            const int row = arow + j * 64;
            cp16(st + (uint32_t)(row * RSTRIDE + q4 * 16),
                 A + (size_t)row * lda + kb + q4 * 8);
        }
        cp16(st + BB_B_OFF + (uint32_t)(arow * RSTRIDE + q4 * 16),
             B + (size_t)arow * ldb + kb + q4 * 8);
    };

    issue(0, 0);
    CP_COMMIT();

    const int KT = K >> 5;
    for (int kt = 0; kt < KT; ++kt) {
        if (kt + 1 < KT) {
            issue((kt + 1) & 1, (kt + 1) << 5);
            CP_COMMIT();
            CP_WAIT(1);
        } else {
            CP_WAIT(0);
        }
        __syncthreads();

        const uint32_t st = sbase + (uint32_t)((kt & 1) * BSTG);
        #pragma unroll
        for (int ks = 0; ks < 2; ++ks) {
            uint32_t ah[2][4], bh[2][4];
            #pragma unroll
            for (int bm = 0; bm < 2; ++bm) {
                const uint32_t aaddr = st + (a_row + bm * 16) * RSTRIDE + ks * 32 + a_co;
                ldsm_x4(ah[bm][0], ah[bm][1], ah[bm][2], ah[bm][3], aaddr);
            }
            #pragma unroll
            for (int np = 0; np < 2; ++np) {
                const uint32_t baddr = st + BB_B_OFF + (b_row + np * 16) * RSTRIDE + ks * 32 + b_co;
                ldsm_x4(bh[np][0], bh[np][1], bh[np][2], bh[np][3], baddr);
            }
            #pragma unroll
            for (int np = 0; np < 2; ++np)
                #pragma unroll
                for (int bm = 0; bm < 2; ++bm) {
                    mma_bf16(acc[bm][np * 2],     ah[bm], bh[np][0], bh[np][1]);
                    mma_bf16(acc[bm][np * 2 + 1], ah[bm], bh[np][2], bh[np][3]);
                }
        }
        __syncthreads();
    }
}

// ---------------------------------------------------------------------------
// Kernel 0a: weight preconversion
// ---------------------------------------------------------------------------
__global__ __launch_bounds__(256)
void prep_kernel(const float* __restrict__ w1, const float* __restrict__ wf,
                 const float* __restrict__ ws, const float* __restrict__ wg)
{
    const int idx = blockIdx.x * 256 + threadIdx.x;
    const int NW1 = ICH * KCONV;
    if (idx < NW1) {
        float v = w1[idx];
        __nv_bfloat16 h = __float2bfloat16_rn(v);
        g_w1h[idx] = h;
        g_w1l[idx] = __float2bfloat16_rn(v - __bfloat162float(h));
    } else {
        int j = idx - NW1;
        if (j >= 3 * NFC * ICH) return;
        const int which = j >> 15;
        const int e = j & 32767;
        float v = (which == 0 ? wf : which == 1 ? ws : wg)[e];
        __nv_bfloat16 h = __float2bfloat16_rn(v);
        __nv_bfloat16 l = __float2bfloat16_rn(v - __bfloat162float(h));
        if (which == 0)      { g_wfh[e] = h; g_wfl[e] = l; }
        else if (which == 1) { g_wsh[e] = h; g_wsl[e] = l; }
        else                 { g_wgh[e] = h; g_wgl[e] = l; }
    }
}

// ---------------------------------------------------------------------------
// Kernel 0b: im2col of x into bf16 hi/lo
// ---------------------------------------------------------------------------
#define I2C_RS 264
#define I2C_SMEM (2 * 64 * I2C_RS * 2)

__global__ __launch_bounds__(256, 1)
void im2col_kernel(const float* __restrict__ x)
{
    extern __shared__ char smraw[];
    __nv_bfloat16* sh = (__nv_bfloat16*)smraw;
    __nv_bfloat16* sl = (__nv_bfloat16*)(smraw + 64 * I2C_RS * 2);

    const int bx = blockIdx.x;
    const int icc = bx & 7;
    const int oh  = (bx >> 3) & 31;
    const int b   = bx >> 8;
    const int t = threadIdx.x;

    #pragma unroll
    for (int it = 0; it < 16; ++it) {
        const int f = t + it * 256;
        const int w4 = f & 63;
        const int kh = (f >> 6) & 7;
        const int i  = f >> 9;
        const float4 v = *(const float4*)&x[((size_t)(b * 64 + icc * 8 + i) * 256 + oh * 8 + kh) * 256 + w4 * 4];
        const int row = i * 8 + kh;
        __nv_bfloat16 h0 = __float2bfloat16_rn(v.x), h1 = __float2bfloat16_rn(v.y);
        __nv_bfloat16 h2 = __float2bfloat16_rn(v.z), h3 = __float2bfloat16_rn(v.w);
        sh[row * I2C_RS + w4 * 4 + 0] = h0;
        sh[row * I2C_RS + w4 * 4 + 1] = h1;
        sh[row * I2C_RS + w4 * 4 + 2] = h2;
        sh[row * I2C_RS + w4 * 4 + 3] = h3;
        sl[row * I2C_RS + w4 * 4 + 0] = __float2bfloat16_rn(v.x - __bfloat162float(h0));
        sl[row * I2C_RS + w4 * 4 + 1] = __float2bfloat16_rn(v.y - __bfloat162float(h1));
        sl[row * I2C_RS + w4 * 4 + 2] = __float2bfloat16_rn(v.z - __bfloat162float(h2));
        sl[row * I2C_RS + w4 * 4 + 3] = __float2bfloat16_rn(v.w - __bfloat162float(h3));
    }
    __syncthreads();

    #pragma unroll
    for (int it = 0; it < 8; ++it) {
        const int f = t + it * 256;
        const int kh = f & 7;
        const int i  = (f >> 3) & 7;
        const int ow = f >> 6;
        const int row = i * 8 + kh;
        const size_t r = (size_t)b * 1024 + oh * 32 + ow;
        const size_t kbase = (size_t)(icc * 8 + i) * 64 + kh * 8;
        *(uint4*)&g_xh[r * KCONV + kbase] = *(const uint4*)&sh[row * I2C_RS + ow * 8];
        *(uint4*)&g_xl[r * KCONV + kbase] = *(const uint4*)&sl[row * I2C_RS + ow * 8];
    }
}

// ---------------------------------------------------------------------------
// Kernel 1: conv1 GEMM (split precision); grid (64 m, 4 n)
// ---------------------------------------------------------------------------
__global__ __launch_bounds__(256, 2)
void conv1_mma_kernel(const float* __restrict__ bnS, const float* __restrict__ bnB)
{
    extern __shared__ char smem[];
    const uint32_t sbase = smem_u32(smem);

    const int m0 = blockIdx.x * 128;
    const int n0 = blockIdx.y * 64;

    float acc[2][4][4] = {};
    gemm_tile_128x64(g_xh + (size_t)m0 * KCONV, g_xl + (size_t)m0 * KCONV, KCONV,
                     g_w1h + (size_t)n0 * KCONV, g_w1l + (size_t)n0 * KCONV, KCONV,
                     KCONV, sbase, acc);

    const int wid = threadIdx.x >> 5, l = threadIdx.x & 31;
    const int erow0 = m0 + (wid & 3) * 32 + (l >> 2);
    const int ecol0 = n0 + (wid >> 2) * 32 + (l & 3) * 2;
    #pragma unroll
    for (int bm = 0; bm < 2; ++bm) {
        #pragma unroll
        for (int nb = 0; nb < 4; ++nb) {
            const int col = ecol0 + nb * 8;
            const float s0 = bnS[col], s1 = bnS[col + 1];
            const float v0 = bnB[col], v1 = bnB[col + 1];
            const int r0 = erow0 + bm * 16;
            float a0 = fmaxf(acc[bm][nb][0] * s0 + v0, 0.0f);
            float a1 = fmaxf(acc[bm][nb][1] * s1 + v1, 0.0f);
            float a2 = fmaxf(acc[bm][nb][2] * s0 + v0, 0.0f);
            float a3 = fmaxf(acc[bm][nb][3] * s1 + v1, 0.0f);
            uint32_t ph, pl;
            split2(a0, a1, ph, pl);
            *(uint32_t*)&g_yh[(size_t)r0 * ICH + col] = ph;
            *(uint32_t*)&g_yl[(size_t)r0 * ICH + col] = pl;
            split2(a2, a3, ph, pl);
            *(uint32_t*)&g_yh[(size_t)(r0 + 8) * ICH + col] = ph;
            *(uint32_t*)&g_yl[(size_t)(r0 + 8) * ICH + col] = pl;
        }
    }
}

// ---------------------------------------------------------------------------
// Kernel 2: projections (split GEMM, bf16-only outputs); grid (64 m, 2 n, 3)
// ---------------------------------------------------------------------------
__global__ __launch_bounds__(256, 2)
void proj_mma_kernel(const float* __restrict__ sf, const float* __restrict__ bf,
                     const float* __restrict__ ss, const float* __restrict__ bs,
                     const float* __restrict__ sg, const float* __restrict__ bg)
{
    extern __shared__ char smem[];
    const uint32_t sbase = smem_u32(smem);

    const int z = blockIdx.z;
    const __nv_bfloat16* Wh = (z == 0) ? g_wfh : (z == 1) ? g_wsh : g_wgh;
    const __nv_bfloat16* Wl = (z == 0) ? g_wfl : (z == 1) ? g_wsl : g_wgl;
    const float* Sv = (z == 0) ? sf : (z == 1) ? ss : sg;
    const float* Bv = (z == 0) ? bf : (z == 1) ? bs : bg;

    const int m0 = blockIdx.x * 128;
    const int n0 = blockIdx.y * 64;

    float acc[2][4][4] = {};
    gemm_tile_128x64(g_yh + (size_t)m0 * ICH, g_yl + (size_t)m0 * ICH, ICH,
                     Wh + (size_t)n0 * ICH, Wl + (size_t)n0 * ICH, ICH,
                     ICH, sbase, acc);

    const int wid = threadIdx.x >> 5, l = threadIdx.x & 31;
    const int erow0 = m0 + (wid & 3) * 32 + (l >> 2);
    const int ecol0 = n0 + (wid >> 2) * 32 + (l & 3) * 2;
    #pragma unroll
    for (int bm = 0; bm < 2; ++bm) {
        #pragma unroll
        for (int nb = 0; nb < 4; ++nb) {
            const int col = ecol0 + nb * 8;
            const float s0 = Sv[col], s1 = Sv[col + 1];
            const float v0 = Bv[col], v1 = Bv[col + 1];
            const int r0 = erow0 + bm * 16;
            float a0 = fmaxf(acc[bm][nb][0] * s0 + v0, 0.0f);
            float a1 = fmaxf(acc[bm][nb][1] * s1 + v1, 0.0f);
            float a2 = fmaxf(acc[bm][nb][2] * s0 + v0, 0.0f);
            float a3 = fmaxf(acc[bm][nb][3] * s1 + v1, 0.0f);
            if (z < 2) {
                __nv_bfloat16* Oh = (z == 0) ? g_faih : g_sith;
                *(uint32_t*)&Oh[(size_t)r0 * NFC + col] = packbf2(a0, a1);
                *(uint32_t*)&Oh[(size_t)(r0 + 8) * NFC + col] = packbf2(a2, a3);
            } else {
                const int bb = r0 >> 10;
                const int n  = r0 & 1023;
                const size_t base = (size_t)bb * NFC * NPIX;
                g_gTh[base + (size_t)col * NPIX + n]            = __float2bfloat16_rn(a0);
                g_gTh[base + (size_t)(col + 1) * NPIX + n]      = __float2bfloat16_rn(a1);
                g_gTh[base + (size_t)col * NPIX + n + 8]        = __float2bfloat16_rn(a2);
                g_gTh[base + (size_t)(col + 1) * NPIX + n + 8]  = __float2bfloat16_rn(a3);
            }
        }
    }
}

// ---------------------------------------------------------------------------
// Kernel 3: score S = sigmoid(fai . sit), pure bf16; grid (8 m, 16 n, 8 b)
// ---------------------------------------------------------------------------
__global__ __launch_bounds__(256, 2)
void score_mma_kernel()
{
    extern __shared__ char smem[];
    const uint32_t sbase = smem_u32(smem);

    const int b  = blockIdx.z;
    const int m0 = blockIdx.x * 128;
    const int n0 = blockIdx.y * 64;
    const size_t abase = (size_t)b * NPIX * NFC;

    float acc[2][4][4] = {};
    gemm_tile_128x64_b16(g_faih + abase + (size_t)m0 * NFC, NFC,
                         g_sith + abase + (size_t)n0 * NFC, NFC,
                         NFC, sbase, acc);

    const size_t sb_out = (size_t)b * NPIX * NPIX;
    const int wid = threadIdx.x >> 5, l = threadIdx.x & 31;
    const int erow0 = m0 + (wid & 3) * 32 + (l >> 2);
    const int ecol0 = n0 + (wid >> 2) * 32 + (l & 3) * 2;
    #pragma unroll
    for (int bm = 0; bm < 2; ++bm) {
        #pragma unroll
        for (int nb = 0; nb < 4; ++nb) {
            const int col = ecol0 + nb * 8;
            const int r0 = erow0 + bm * 16;
            float a0 = 1.0f / (1.0f + expf(-acc[bm][nb][0]));
            float a1 = 1.0f / (1.0f + expf(-acc[bm][nb][1]));
            float a2 = 1.0f / (1.0f + expf(-acc[bm][nb][2]));
            float a3 = 1.0f / (1.0f + expf(-acc[bm][nb][3]));
            *(uint32_t*)&g_Sh[sb_out + (size_t)r0 * NPIX + col] = packbf2(a0, a1);
            *(uint32_t*)&g_Sh[sb_out + (size_t)(r0 + 8) * NPIX + col] = packbf2(a2, a3);
        }
    }
}

// ---------------------------------------------------------------------------
// Kernel 4: att = S @ gamaT, pure bf16, split-K(2); grid (8 m, 2 n, 16)
// ---------------------------------------------------------------------------
__global__ __launch_bounds__(256, 2)
void attn_mma_kernel()
{
    extern __shared__ char smem[];
    const uint32_t sbase = smem_u32(smem);

    const int z  = blockIdx.z;
    const int b  = z >> 1;
    const int ks = z & 1;
    const int m0 = blockIdx.x * 128;
    const int n0 = blockIdx.y * 64;
    const size_t sBase = (size_t)b * NPIX * NPIX;
    const size_t gBase = (size_t)b * NFC * NPIX;
    const int kofs = ks * 512;

    float acc[2][4][4] = {};
    gemm_tile_128x64_b16(g_Sh + sBase + (size_t)m0 * NPIX + kofs, NPIX,
                         g_gTh + gBase + (size_t)n0 * NPIX + kofs, NPIX,
                         512, sbase, acc);

    float* outp = ks ? g_att1 : g_att0;
    const int wid = threadIdx.x >> 5, l = threadIdx.x & 31;
    const int erow0 = m0 + (wid & 3) * 32 + (l >> 2);
    const int ecol0 = n0 + (wid >> 2) * 32 + (l & 3) * 2;
    #pragma unroll
    for (int bm = 0; bm < 2; ++bm) {
        #pragma unroll
        for (int nb = 0; nb < 4; ++nb) {
            const int col = ecol0 + nb * 8;
            const int r0 = erow0 + bm * 16;
            float2 o0 = {acc[bm][nb][0], acc[bm][nb][1]};
            float2 o1 = {acc[bm][nb][2], acc[bm][nb][3]};
            *(float2*)&outp[((size_t)b * NPIX + r0) * NFC + col] = o0;
            *(float2*)&outp[((size_t)b * NPIX + r0 + 8) * NFC + col] = o1;
        }
    }
}

// ---------------------------------------------------------------------------
// Kernel 5: bilinear upsample x8 (align_corners), sums split-K partials
// ---------------------------------------------------------------------------
__global__ __launch_bounds__(256)
void upsample_kernel(float* __restrict__ out)
{
    __shared__ float rows[3][32];
    const int gx = blockIdx.x;
    const int yt = gx & 31;
    const int c  = (gx >> 5) & 127;
    const int b  = gx >> 12;
    const int t = threadIdx.x;

    const float sc = 31.0f / 255.0f;
    const int rbase = (int)floorf((float)(yt * 8) * sc);
    if (t < 96) {
        const int rr = t >> 5, xx = t & 31;
        const int r = min(rbase + rr, 31);
        const size_t idx = ((size_t)b * NPIX + r * 32 + xx) * NFC + c;
        rows[rr][xx] = g_att0[idx] + g_att1[idx];
    }
    __syncthreads();

    const int xo = t;
    const float xs = (float)xo * sc;
    const int x0 = (int)floorf(xs);
    const float wx = xs - (float)x0;
    const int x1 = min(x0 + 1, 31);
    const size_t obase = ((size_t)(b * 128 + c)) * 256 * 256;

    #pragma unroll
    for (int i = 0; i < 8; ++i) {
        const int yo = yt * 8 + i;
        const float ysf = (float)yo * sc;
        const int y0 = (int)floorf(ysf);
        const float wy = ysf - (float)y0;
        const int y1 = min(y0 + 1, 31);
        const int r0 = y0 - rbase, r1 = y1 - rbase;
        const float v00 = rows[r0][x0], v01 = rows[r0][x1];
        const float v10 = rows[r1][x0], v11 = rows[r1][x1];
        const float top0 = v00 * (1.0f - wy) + v10 * wy;
        const float top1 = v01 * (1.0f - wy) + v11 * wy;
        out[obase + (size_t)yo * 256 + xo] = top0 * (1.0f - wx) + top1 * wx;
    }
}

// ---------------------------------------------------------------------------
// Launch
// ---------------------------------------------------------------------------
extern "C" void kernel_launch(void* const* d_in, const int* in_sizes, int n_in,
                              void* d_out, int out_size)
{
    const float* x     = (const float*)d_in[0];
    const float* w1    = (const float*)d_in[1];
    const float* bn1_s = (const float*)d_in[2];
    const float* bn1_b = (const float*)d_in[3];
    const float* w_fai = (const float*)d_in[4];
    const float* bnf_s = (const float*)d_in[5];
    const float* bnf_b = (const float*)d_in[6];
    const float* w_sit = (const float*)d_in[7];
    const float* bns_s = (const float*)d_in[8];
    const float* bns_b = (const float*)d_in[9];
    const float* w_gam = (const float*)d_in[10];
    const float* bng_s = (const float*)d_in[11];
    const float* bng_b = (const float*)d_in[12];
    float* out = (float*)d_out;

    static bool attr_done = false;
    if (!attr_done) {
        cudaFuncSetAttribute(conv1_mma_kernel, cudaFuncAttributeMaxDynamicSharedMemorySize, GEMM_SMEM2);
        cudaFuncSetAttribute(proj_mma_kernel,  cudaFuncAttributeMaxDynamicSharedMemorySize, GEMM_SMEM2);
        cudaFuncSetAttribute(score_mma_kernel, cudaFuncAttributeMaxDynamicSharedMemorySize, GEMM_SMEM_B16);
        cudaFuncSetAttribute(attn_mma_kernel,  cudaFuncAttributeMaxDynamicSharedMemorySize, GEMM_SMEM_B16);
        cudaFuncSetAttribute(im2col_kernel,    cudaFuncAttributeMaxDynamicSharedMemorySize, I2C_SMEM);
        attr_done = true;
    }

    // 0a. weight preconversion
    {
        const int total = ICH * KCONV + 3 * NFC * ICH;
        prep_kernel<<<(total + 255) / 256, 256>>>(w1, w_fai, w_sit, w_gam);
    }
    // 0b. im2col(x) -> bf16 hi/lo
    im2col_kernel<<<2048, 256, I2C_SMEM>>>(x);
    // 1. conv1 GEMM + BN + ReLU
    {
        dim3 grid(MROWS / 128, ICH / 64);
        conv1_mma_kernel<<<grid, 256, GEMM_SMEM2>>>(bn1_s, bn1_b);
    }
    // 2. projections
    {
        dim3 grid(MROWS / 128, NFC / 64, 3);
        proj_mma_kernel<<<grid, 256, GEMM_SMEM2>>>(bnf_s, bnf_b, bns_s, bns_b, bng_s, bng_b);
    }
    // 3. S = sigmoid(fai . sit), pure bf16
    {
        dim3 grid(NPIX / 128, NPIX / 64, BATCH);
        score_mma_kernel<<<grid, 256, GEMM_SMEM_B16>>>();
    }
    // 4. att = S @ gamaT, pure bf16, split-K 2
    {
        dim3 grid(NPIX / 128, NFC / 64, BATCH * 2);
        attn_mma_kernel<<<grid, 256, GEMM_SMEM_B16>>>();
    }
    // 5. upsample (+ split-K reduce)
    upsample_kernel<<<BATCH * 128 * 32, 256>>>(out);
}

// round 11
// speedup vs baseline: 1.5212x; 1.2757x over previous
#include <cuda_runtime.h>
#include <cuda_fp16.h>
#include <math.h>
#include <stdint.h>

// ---------------------------------------------------------------------------
// Problem constants
// ---------------------------------------------------------------------------
#define BATCH 8
#define ICH   256
#define NFC   128
#define NPIX  1024
#define KCONV 4096
#define MROWS 8192

// ---------------------------------------------------------------------------
// Device scratch (fp16 chain; weights split hi/lo, activations single)
// ---------------------------------------------------------------------------
__device__ __half g_w1h[ICH * KCONV], g_w1l[ICH * KCONV];
__device__ __half g_wfh[NFC * ICH],  g_wfl[NFC * ICH];
__device__ __half g_wsh[NFC * ICH],  g_wsl[NFC * ICH];
__device__ __half g_wgh[NFC * ICH],  g_wgl[NFC * ICH];

__device__ __half g_x[MROWS * KCONV];          // im2col(x), single fp16
__device__ __half g_y[MROWS * ICH];            // conv out, single fp16
__device__ __half g_fai[BATCH * NPIX * NFC];
__device__ __half g_sit[BATCH * NPIX * NFC];
__device__ __half g_gT[BATCH * NFC * NPIX];    // [b][c][m]
__device__ __half g_S[BATCH * NPIX * NPIX];    // [b][n][m]
__device__ float g_att0[BATCH * NPIX * NFC];   // split-K partials
__device__ float g_att1[BATCH * NPIX * NFC];

// ---------------------------------------------------------------------------
// Portable helpers (base sm_103)
// ---------------------------------------------------------------------------
__device__ __forceinline__ uint32_t smem_u32(const void* p) {
    uint32_t a;
    asm("{ .reg .u64 t; cvta.to.shared.u64 t, %1; cvt.u32.u64 %0, t; }" : "=r"(a) : "l"(p));
    return a;
}

__device__ __forceinline__ void cp16(uint32_t saddr, const void* gaddr) {
    asm volatile("cp.async.cg.shared.global [%0], [%1], 16;" :: "r"(saddr), "l"(gaddr));
}
#define CP_COMMIT() asm volatile("cp.async.commit_group;" ::: "memory")
#define CP_WAIT(n)  asm volatile("cp.async.wait_group %0;" :: "n"(n) : "memory")

__device__ __forceinline__ void ldsm_x4(uint32_t& r0, uint32_t& r1, uint32_t& r2, uint32_t& r3,
                                        uint32_t addr) {
    asm volatile("ldmatrix.sync.aligned.m8n8.x4.shared.b16 {%0,%1,%2,%3}, [%4];"
        : "=r"(r0), "=r"(r1), "=r"(r2), "=r"(r3) : "r"(addr));
}

__device__ __forceinline__ void mma_f16(float* c, const uint32_t* a,
                                        uint32_t b0, uint32_t b1) {
    asm volatile(
        "mma.sync.aligned.m16n8k16.row.col.f32.f16.f16.f32 "
        "{%0,%1,%2,%3}, {%4,%5,%6,%7}, {%8,%9}, {%0,%1,%2,%3};"
        : "+f"(c[0]), "+f"(c[1]), "+f"(c[2]), "+f"(c[3])
        : "r"(a[0]), "r"(a[1]), "r"(a[2]), "r"(a[3]), "r"(b0), "r"(b1));
}

__device__ __forceinline__ uint32_t packh2(float a, float b) {
    __half h0 = __float2half_rn(a), h1 = __float2half_rn(b);
    return (uint32_t)__half_as_ushort(h0) | ((uint32_t)__half_as_ushort(h1) << 16);
}

#define RSTRIDE 80

// ---------------------------------------------------------------------------
// Tile variant 1: A single fp16, B split hi/lo fp16 (2 products)
//   smem/stage: A[128x32]@0 (10240) + Bh[64x32]@10240 (5120) + Bl@15360 (5120)
// ---------------------------------------------------------------------------
#define AS_BH 10240
#define AS_BL 15360
#define AS_STG 20480
#define GEMM_SMEM_AS (2 * AS_STG)   // 40960

__device__ __forceinline__ void gemm_tile_as_bsplit(
    const __half* __restrict__ A, int lda,
    const __half* __restrict__ Bh, const __half* __restrict__ Bl, int ldb,
    int K, uint32_t sbase, float acc[2][4][4])
{
    const int tid = threadIdx.x;
    const int l = tid & 31;
    const int wid = tid >> 5;
    const int warp_m = wid & 3, warp_n = wid >> 2;
    const int arow = tid >> 2;
    const int q4   = tid & 3;

    const uint32_t a_row = (uint32_t)(warp_m * 32 + (l & 15));
    const uint32_t a_co  = (uint32_t)((l >> 4) << 4);
    const uint32_t b_row = (uint32_t)(warp_n * 32 + (l & 7) + ((l >> 4) & 1) * 8);
    const uint32_t b_co  = (uint32_t)(((l >> 3) & 1) << 4);

    auto issue = [&](int s, int kb) {
        const uint32_t st = sbase + (uint32_t)s * AS_STG;
        #pragma unroll
        for (int j = 0; j < 2; ++j) {
            const int row = arow + j * 64;
            cp16(st + (uint32_t)(row * RSTRIDE + q4 * 16),
                 A + (size_t)row * lda + kb + q4 * 8);
        }
        const uint32_t so = st + (uint32_t)(arow * RSTRIDE + q4 * 16);
        cp16(so + AS_BH, Bh + (size_t)arow * ldb + kb + q4 * 8);
        cp16(so + AS_BL, Bl + (size_t)arow * ldb + kb + q4 * 8);
    };

    issue(0, 0);
    CP_COMMIT();

    const int KT = K >> 5;
    for (int kt = 0; kt < KT; ++kt) {
        if (kt + 1 < KT) {
            issue((kt + 1) & 1, (kt + 1) << 5);
            CP_COMMIT();
            CP_WAIT(1);
        } else {
            CP_WAIT(0);
        }
        __syncthreads();

        const uint32_t st = sbase + (uint32_t)((kt & 1) * AS_STG);
        #pragma unroll
        for (int ks = 0; ks < 2; ++ks) {
            uint32_t ah[2][4], bh[2][4], bl[2][4];
            #pragma unroll
            for (int bm = 0; bm < 2; ++bm) {
                const uint32_t aaddr = st + (a_row + bm * 16) * RSTRIDE + ks * 32 + a_co;
                ldsm_x4(ah[bm][0], ah[bm][1], ah[bm][2], ah[bm][3], aaddr);
            }
            #pragma unroll
            for (int np = 0; np < 2; ++np) {
                const uint32_t baddr = st + AS_BH + (b_row + np * 16) * RSTRIDE + ks * 32 + b_co;
                ldsm_x4(bh[np][0], bh[np][1], bh[np][2], bh[np][3], baddr);
                ldsm_x4(bl[np][0], bl[np][1], bl[np][2], bl[np][3], baddr + (AS_BL - AS_BH));
            }
            #pragma unroll
            for (int np = 0; np < 2; ++np)
                #pragma unroll
                for (int bm = 0; bm < 2; ++bm) {
                    mma_f16(acc[bm][np * 2],     ah[bm], bh[np][0], bh[np][1]);
                    mma_f16(acc[bm][np * 2 + 1], ah[bm], bh[np][2], bh[np][3]);
                }
            #pragma unroll
            for (int np = 0; np < 2; ++np)
                #pragma unroll
                for (int bm = 0; bm < 2; ++bm) {
                    mma_f16(acc[bm][np * 2],     ah[bm], bl[np][0], bl[np][1]);
                    mma_f16(acc[bm][np * 2 + 1], ah[bm], bl[np][2], bl[np][3]);
                }
        }
        __syncthreads();
    }
}

// ---------------------------------------------------------------------------
// Tile variant 2: both single fp16 (1 product) — score / attn
// ---------------------------------------------------------------------------
#define SS_B  10240
#define SS_STG 15360
#define GEMM_SMEM_SS (2 * SS_STG)   // 30720

__device__ __forceinline__ void gemm_tile_ss(
    const __half* __restrict__ A, int lda,
    const __half* __restrict__ B, int ldb,
    int K, uint32_t sbase, float acc[2][4][4])
{
    const int tid = threadIdx.x;
    const int l = tid & 31;
    const int wid = tid >> 5;
    const int warp_m = wid & 3, warp_n = wid >> 2;
    const int arow = tid >> 2;
    const int q4   = tid & 3;

    const uint32_t a_row = (uint32_t)(warp_m * 32 + (l & 15));
    const uint32_t a_co  = (uint32_t)((l >> 4) << 4);
    const uint32_t b_row = (uint32_t)(warp_n * 32 + (l & 7) + ((l >> 4) & 1) * 8);
    const uint32_t b_co  = (uint32_t)(((l >> 3) & 1) << 4);

    auto issue = [&](int s, int kb) {
        const uint32_t st = sbase + (uint32_t)s * SS_STG;
        #pragma unroll
        for (int j = 0; j < 2; ++j) {
            const int row = arow + j * 64;
            cp16(st + (uint32_t)(row * RSTRIDE + q4 * 16),
                 A + (size_t)row * lda + kb + q4 * 8);
        }
        cp16(st + SS_B + (uint32_t)(arow * RSTRIDE + q4 * 16),
             B + (size_t)arow * ldb + kb + q4 * 8);
    };

    issue(0, 0);
    CP_COMMIT();

    const int KT = K >> 5;
    for (int kt = 0; kt < KT; ++kt) {
        if (kt + 1 < KT) {
            issue((kt + 1) & 1, (kt + 1) << 5);
            CP_COMMIT();
            CP_WAIT(1);
        } else {
            CP_WAIT(0);
        }
        __syncthreads();

        const uint32_t st = sbase + (uint32_t)((kt & 1) * SS_STG);
        #pragma unroll
        for (int ks = 0; ks < 2; ++ks) {
            uint32_t ah[2][4], bh[2][4];
            #pragma unroll
            for (int bm = 0; bm < 2; ++bm) {
                const uint32_t aaddr = st + (a_row + bm * 16) * RSTRIDE + ks * 32 + a_co;
                ldsm_x4(ah[bm][0], ah[bm][1], ah[bm][2], ah[bm][3], aaddr);
            }
            #pragma unroll
            for (int np = 0; np < 2; ++np) {
                const uint32_t baddr = st + SS_B + (b_row + np * 16) * RSTRIDE + ks * 32 + b_co;
                ldsm_x4(bh[np][0], bh[np][1], bh[np][2], bh[np][3], baddr);
            }
            #pragma unroll
            for (int np = 0; np < 2; ++np)
                #pragma unroll
                for (int bm = 0; bm < 2; ++bm) {
                    mma_f16(acc[bm][np * 2],     ah[bm], bh[np][0], bh[np][1]);
                    mma_f16(acc[bm][np * 2 + 1], ah[bm], bh[np][2], bh[np][3]);
                }
        }
        __syncthreads();
    }
}

// ---------------------------------------------------------------------------
// Kernel 0a: weight preconversion (fp16 hi/lo)
// ---------------------------------------------------------------------------
__global__ __launch_bounds__(256)
void prep_kernel(const float* __restrict__ w1, const float* __restrict__ wf,
                 const float* __restrict__ ws, const float* __restrict__ wg)
{
    const int idx = blockIdx.x * 256 + threadIdx.x;
    const int NW1 = ICH * KCONV;
    if (idx < NW1) {
        float v = w1[idx];
        __half h = __float2half_rn(v);
        g_w1h[idx] = h;
        g_w1l[idx] = __float2half_rn(v - __half2float(h));
    } else {
        int j = idx - NW1;
        if (j >= 3 * NFC * ICH) return;
        const int which = j >> 15;
        const int e = j & 32767;
        float v = (which == 0 ? wf : which == 1 ? ws : wg)[e];
        __half h = __float2half_rn(v);
        __half lo = __float2half_rn(v - __half2float(h));
        if (which == 0)      { g_wfh[e] = h; g_wfl[e] = lo; }
        else if (which == 1) { g_wsh[e] = h; g_wsl[e] = lo; }
        else                 { g_wgh[e] = h; g_wgl[e] = lo; }
    }
}

// ---------------------------------------------------------------------------
// Kernel 0b: im2col of x into single fp16
// ---------------------------------------------------------------------------
#define I2C_RS 264
#define I2C_SMEM (64 * I2C_RS * 2)

__global__ __launch_bounds__(256, 1)
void im2col_kernel(const float* __restrict__ x)
{
    extern __shared__ char smraw[];
    __half* sh = (__half*)smraw;

    const int bx = blockIdx.x;
    const int icc = bx & 7;
    const int oh  = (bx >> 3) & 31;
    const int b   = bx >> 8;
    const int t = threadIdx.x;

    #pragma unroll
    for (int it = 0; it < 16; ++it) {
        const int f = t + it * 256;
        const int w4 = f & 63;
        const int kh = (f >> 6) & 7;
        const int i  = f >> 9;
        const float4 v = *(const float4*)&x[((size_t)(b * 64 + icc * 8 + i) * 256 + oh * 8 + kh) * 256 + w4 * 4];
        const int row = i * 8 + kh;
        sh[row * I2C_RS + w4 * 4 + 0] = __float2half_rn(v.x);
        sh[row * I2C_RS + w4 * 4 + 1] = __float2half_rn(v.y);
        sh[row * I2C_RS + w4 * 4 + 2] = __float2half_rn(v.z);
        sh[row * I2C_RS + w4 * 4 + 3] = __float2half_rn(v.w);
    }
    __syncthreads();

    #pragma unroll
    for (int it = 0; it < 8; ++it) {
        const int f = t + it * 256;
        const int kh = f & 7;
        const int i  = (f >> 3) & 7;
        const int ow = f >> 6;
        const int row = i * 8 + kh;
        const size_t r = (size_t)b * 1024 + oh * 32 + ow;
        const size_t kbase = (size_t)(icc * 8 + i) * 64 + kh * 8;
        *(uint4*)&g_x[r * KCONV + kbase] = *(const uint4*)&sh[row * I2C_RS + ow * 8];
    }
}

// ---------------------------------------------------------------------------
// Kernel 1: conv1 GEMM (A single, W split); grid (64 m, 4 n)
// ---------------------------------------------------------------------------
__global__ __launch_bounds__(256, 2)
void conv1_mma_kernel(const float* __restrict__ bnS, const float* __restrict__ bnB)
{
    extern __shared__ char smem[];
    const uint32_t sbase = smem_u32(smem);

    const int m0 = blockIdx.x * 128;
    const int n0 = blockIdx.y * 64;

    float acc[2][4][4] = {};
    gemm_tile_as_bsplit(g_x + (size_t)m0 * KCONV, KCONV,
                        g_w1h + (size_t)n0 * KCONV, g_w1l + (size_t)n0 * KCONV, KCONV,
                        KCONV, sbase, acc);

    const int wid = threadIdx.x >> 5, l = threadIdx.x & 31;
    const int erow0 = m0 + (wid & 3) * 32 + (l >> 2);
    const int ecol0 = n0 + (wid >> 2) * 32 + (l & 3) * 2;
    #pragma unroll
    for (int bm = 0; bm < 2; ++bm) {
        #pragma unroll
        for (int nb = 0; nb < 4; ++nb) {
            const int col = ecol0 + nb * 8;
            const float s0 = bnS[col], s1 = bnS[col + 1];
            const float v0 = bnB[col], v1 = bnB[col + 1];
            const int r0 = erow0 + bm * 16;
            float a0 = fmaxf(acc[bm][nb][0] * s0 + v0, 0.0f);
            float a1 = fmaxf(acc[bm][nb][1] * s1 + v1, 0.0f);
            float a2 = fmaxf(acc[bm][nb][2] * s0 + v0, 0.0f);
            float a3 = fmaxf(acc[bm][nb][3] * s1 + v1, 0.0f);
            *(uint32_t*)&g_y[(size_t)r0 * ICH + col] = packh2(a0, a1);
            *(uint32_t*)&g_y[(size_t)(r0 + 8) * ICH + col] = packh2(a2, a3);
        }
    }
}

// ---------------------------------------------------------------------------
// Kernel 2: projections (y single, W split); grid (64 m, 2 n, 3)
// ---------------------------------------------------------------------------
__global__ __launch_bounds__(256, 2)
void proj_mma_kernel(const float* __restrict__ sf, const float* __restrict__ bf,
                     const float* __restrict__ ss, const float* __restrict__ bs,
                     const float* __restrict__ sg, const float* __restrict__ bg)
{
    extern __shared__ char smem[];
    const uint32_t sbase = smem_u32(smem);

    const int z = blockIdx.z;
    const __half* Wh = (z == 0) ? g_wfh : (z == 1) ? g_wsh : g_wgh;
    const __half* Wl = (z == 0) ? g_wfl : (z == 1) ? g_wsl : g_wgl;
    const float* Sv = (z == 0) ? sf : (z == 1) ? ss : sg;
    const float* Bv = (z == 0) ? bf : (z == 1) ? bs : bg;

    const int m0 = blockIdx.x * 128;
    const int n0 = blockIdx.y * 64;

    float acc[2][4][4] = {};
    gemm_tile_as_bsplit(g_y + (size_t)m0 * ICH, ICH,
                        Wh + (size_t)n0 * ICH, Wl + (size_t)n0 * ICH, ICH,
                        ICH, sbase, acc);

    const int wid = threadIdx.x >> 5, l = threadIdx.x & 31;
    const int erow0 = m0 + (wid & 3) * 32 + (l >> 2);
    const int ecol0 = n0 + (wid >> 2) * 32 + (l & 3) * 2;
    #pragma unroll
    for (int bm = 0; bm < 2; ++bm) {
        #pragma unroll
        for (int nb = 0; nb < 4; ++nb) {
            const int col = ecol0 + nb * 8;
            const float s0 = Sv[col], s1 = Sv[col + 1];
            const float v0 = Bv[col], v1 = Bv[col + 1];
            const int r0 = erow0 + bm * 16;
            float a0 = fmaxf(acc[bm][nb][0] * s0 + v0, 0.0f);
            float a1 = fmaxf(acc[bm][nb][1] * s1 + v1, 0.0f);
            float a2 = fmaxf(acc[bm][nb][2] * s0 + v0, 0.0f);
            float a3 = fmaxf(acc[bm][nb][3] * s1 + v1, 0.0f);
            if (z < 2) {
                __half* Oh = (z == 0) ? g_fai : g_sit;
                *(uint32_t*)&Oh[(size_t)r0 * NFC + col] = packh2(a0, a1);
                *(uint32_t*)&Oh[(size_t)(r0 + 8) * NFC + col] = packh2(a2, a3);
            } else {
                const int bb = r0 >> 10;
                const int n  = r0 & 1023;
                const size_t base = (size_t)bb * NFC * NPIX;
                g_gT[base + (size_t)col * NPIX + n]            = __float2half_rn(a0);
                g_gT[base + (size_t)(col + 1) * NPIX + n]      = __float2half_rn(a1);
                g_gT[base + (size_t)col * NPIX + n + 8]        = __float2half_rn(a2);
                g_gT[base + (size_t)(col + 1) * NPIX + n + 8]  = __float2half_rn(a3);
            }
        }
    }
}

// ---------------------------------------------------------------------------
// Kernel 3: score S = sigmoid(fai . sit); grid (8 m, 16 n, 8 b)
// ---------------------------------------------------------------------------
__global__ __launch_bounds__(256, 2)
void score_mma_kernel()
{
    extern __shared__ char smem[];
    const uint32_t sbase = smem_u32(smem);

    const int b  = blockIdx.z;
    const int m0 = blockIdx.x * 128;
    const int n0 = blockIdx.y * 64;
    const size_t abase = (size_t)b * NPIX * NFC;

    float acc[2][4][4] = {};
    gemm_tile_ss(g_fai + abase + (size_t)m0 * NFC, NFC,
                 g_sit + abase + (size_t)n0 * NFC, NFC,
                 NFC, sbase, acc);

    const size_t sb_out = (size_t)b * NPIX * NPIX;
    const int wid = threadIdx.x >> 5, l = threadIdx.x & 31;
    const int erow0 = m0 + (wid & 3) * 32 + (l >> 2);
    const int ecol0 = n0 + (wid >> 2) * 32 + (l & 3) * 2;
    #pragma unroll
    for (int bm = 0; bm < 2; ++bm) {
        #pragma unroll
        for (int nb = 0; nb < 4; ++nb) {
            const int col = ecol0 + nb * 8;
            const int r0 = erow0 + bm * 16;
            float a0 = 1.0f / (1.0f + expf(-acc[bm][nb][0]));
            float a1 = 1.0f / (1.0f + expf(-acc[bm][nb][1]));
            float a2 = 1.0f / (1.0f + expf(-acc[bm][nb][2]));
            float a3 = 1.0f / (1.0f + expf(-acc[bm][nb][3]));
            *(uint32_t*)&g_S[sb_out + (size_t)r0 * NPIX + col] = packh2(a0, a1);
            *(uint32_t*)&g_S[sb_out + (size_t)(r0 + 8) * NPIX + col] = packh2(a2, a3);
        }
    }
}

// ---------------------------------------------------------------------------
// Kernel 4: att = S @ gamaT, split-K(2); grid (8 m, 2 n, 16)
// ---------------------------------------------------------------------------
__global__ __launch_bounds__(256, 2)
void attn_mma_kernel()
{
    extern __shared__ char smem[];
    const uint32_t sbase = smem_u32(smem);

    const int z  = blockIdx.z;
    const int b  = z >> 1;
    const int ks = z & 1;
    const int m0 = blockIdx.x * 128;
    const int n0 = blockIdx.y * 64;
    const size_t sBase = (size_t)b * NPIX * NPIX;
    const size_t gBase = (size_t)b * NFC * NPIX;
    const int kofs = ks * 512;

    float acc[2][4][4] = {};
    gemm_tile_ss(g_S + sBase + (size_t)m0 * NPIX + kofs, NPIX,
                 g_gT + gBase + (size_t)n0 * NPIX + kofs, NPIX,
                 512, sbase, acc);

    float* outp = ks ? g_att1 : g_att0;
    const int wid = threadIdx.x >> 5, l = threadIdx.x & 31;
    const int erow0 = m0 + (wid & 3) * 32 + (l >> 2);
    const int ecol0 = n0 + (wid >> 2) * 32 + (l & 3) * 2;
    #pragma unroll
    for (int bm = 0; bm < 2; ++bm) {
        #pragma unroll
        for (int nb = 0; nb < 4; ++nb) {
            const int col = ecol0 + nb * 8;
            const int r0 = erow0 + bm * 16;
            float2 o0 = {acc[bm][nb][0], acc[bm][nb][1]};
            float2 o1 = {acc[bm][nb][2], acc[bm][nb][3]};
            *(float2*)&outp[((size_t)b * NPIX + r0) * NFC + col] = o0;
            *(float2*)&outp[((size_t)b * NPIX + r0 + 8) * NFC + col] = o1;
        }
    }
}

// ---------------------------------------------------------------------------
// Kernel 5: bilinear upsample x8 (align_corners), sums split-K partials
// ---------------------------------------------------------------------------
__global__ __launch_bounds__(256)
void upsample_kernel(float* __restrict__ out)
{
    __shared__ float rows[3][32];
    const int gx = blockIdx.x;
    const int yt = gx & 31;
    const int c  = (gx >> 5) & 127;
    const int b  = gx >> 12;
    const int t = threadIdx.x;

    const float sc = 31.0f / 255.0f;
    const int rbase = (int)floorf((float)(yt * 8) * sc);
    if (t < 96) {
        const int rr = t >> 5, xx = t & 31;
        const int r = min(rbase + rr, 31);
        const size_t idx = ((size_t)b * NPIX + r * 32 + xx) * NFC + c;
        rows[rr][xx] = g_att0[idx] + g_att1[idx];
    }
    __syncthreads();

    const int xo = t;
    const float xs = (float)xo * sc;
    const int x0 = (int)floorf(xs);
    const float wx = xs - (float)x0;
    const int x1 = min(x0 + 1, 31);
    const size_t obase = ((size_t)(b * 128 + c)) * 256 * 256;

    #pragma unroll
    for (int i = 0; i < 8; ++i) {
        const int yo = yt * 8 + i;
        const float ysf = (float)yo * sc;
        const int y0 = (int)floorf(ysf);
        const float wy = ysf - (float)y0;
        const int y1 = min(y0 + 1, 31);
        const int r0 = y0 - rbase, r1 = y1 - rbase;
        const float v00 = rows[r0][x0], v01 = rows[r0][x1];
        const float v10 = rows[r1][x0], v11 = rows[r1][x1];
        const float top0 = v00 * (1.0f - wy) + v10 * wy;
        const float top1 = v01 * (1.0f - wy) + v11 * wy;
        out[obase + (size_t)yo * 256 + xo] = top0 * (1.0f - wx) + top1 * wx;
    }
}

// ---------------------------------------------------------------------------
// Launch
// ---------------------------------------------------------------------------
extern "C" void kernel_launch(void* const* d_in, const int* in_sizes, int n_in,
                              void* d_out, int out_size)
{
    const float* x     = (const float*)d_in[0];
    const float* w1    = (const float*)d_in[1];
    const float* bn1_s = (const float*)d_in[2];
    const float* bn1_b = (const float*)d_in[3];
    const float* w_fai = (const float*)d_in[4];
    const float* bnf_s = (const float*)d_in[5];
    const float* bnf_b = (const float*)d_in[6];
    const float* w_sit = (const float*)d_in[7];
    const float* bns_s = (const float*)d_in[8];
    const float* bns_b = (const float*)d_in[9];
    const float* w_gam = (const float*)d_in[10];
    const float* bng_s = (const float*)d_in[11];
    const float* bng_b = (const float*)d_in[12];
    float* out = (float*)d_out;

    static bool attr_done = false;
    if (!attr_done) {
        cudaFuncSetAttribute(conv1_mma_kernel, cudaFuncAttributeMaxDynamicSharedMemorySize, GEMM_SMEM_AS);
        cudaFuncSetAttribute(proj_mma_kernel,  cudaFuncAttributeMaxDynamicSharedMemorySize, GEMM_SMEM_AS);
        cudaFuncSetAttribute(score_mma_kernel, cudaFuncAttributeMaxDynamicSharedMemorySize, GEMM_SMEM_SS);
        cudaFuncSetAttribute(attn_mma_kernel,  cudaFuncAttributeMaxDynamicSharedMemorySize, GEMM_SMEM_SS);
        cudaFuncSetAttribute(im2col_kernel,    cudaFuncAttributeMaxDynamicSharedMemorySize, I2C_SMEM);
        attr_done = true;
    }

    // 0a. weight preconversion (fp16 hi/lo)
    {
        const int total = ICH * KCONV + 3 * NFC * ICH;
        prep_kernel<<<(total + 255) / 256, 256>>>(w1, w_fai, w_sit, w_gam);
    }
    // 0b. im2col(x) -> single fp16
    im2col_kernel<<<2048, 256, I2C_SMEM>>>(x);
    // 1. conv1 GEMM + BN + ReLU (2-product fp16)
    {
        dim3 grid(MROWS / 128, ICH / 64);
        conv1_mma_kernel<<<grid, 256, GEMM_SMEM_AS>>>(bn1_s, bn1_b);
    }
    // 2. projections (2-product fp16)
    {
        dim3 grid(MROWS / 128, NFC / 64, 3);
        proj_mma_kernel<<<grid, 256, GEMM_SMEM_AS>>>(bnf_s, bnf_b, bns_s, bns_b, bng_s, bng_b);
    }
    // 3. S = sigmoid(fai . sit) (1-product fp16)
    {
        dim3 grid(NPIX / 128, NPIX / 64, BATCH);
        score_mma_kernel<<<grid, 256, GEMM_SMEM_SS>>>();
    }
    // 4. att = S @ gamaT (1-product fp16, split-K 2)
    {
        dim3 grid(NPIX / 128, NFC / 64, BATCH * 2);
        attn_mma_kernel<<<grid, 256, GEMM_SMEM_SS>>>();
    }
    // 5. upsample (+ split-K reduce)
    upsample_kernel<<<BATCH * 128 * 32, 256>>>(out);
}

// round 12
// speedup vs baseline: 1.8051x; 1.1867x over previous
#include <cuda_runtime.h>
#include <cuda_fp16.h>
#include <math.h>
#include <stdint.h>

// ---------------------------------------------------------------------------
// Problem constants
// ---------------------------------------------------------------------------
#define BATCH 8
#define ICH   256
#define NFC   128
#define NPIX  1024
#define KCONV 4096
#define MROWS 8192

// ---------------------------------------------------------------------------
// Device scratch (pure fp16 chain)
// ---------------------------------------------------------------------------
__device__ __half g_w1[ICH * KCONV];
__device__ __half g_wf[NFC * ICH];
__device__ __half g_ws[NFC * ICH];
__device__ __half g_wg[NFC * ICH];

__device__ __half g_x[MROWS * KCONV];          // im2col(x)
__device__ __half g_y[MROWS * ICH];            // conv out
__device__ __half g_fai[BATCH * NPIX * NFC];
__device__ __half g_sit[BATCH * NPIX * NFC];
__device__ __half g_gT[BATCH * NFC * NPIX];    // [b][c][m]
__device__ __half g_S[BATCH * NPIX * NPIX];    // [b][n][m]
__device__ float g_att0[BATCH * NPIX * NFC];   // split-K partials
__device__ float g_att1[BATCH * NPIX * NFC];

// ---------------------------------------------------------------------------
// Portable helpers (base sm_103)
// ---------------------------------------------------------------------------
__device__ __forceinline__ uint32_t smem_u32(const void* p) {
    uint32_t a;
    asm("{ .reg .u64 t; cvta.to.shared.u64 t, %1; cvt.u32.u64 %0, t; }" : "=r"(a) : "l"(p));
    return a;
}

__device__ __forceinline__ void cp16(uint32_t saddr, const void* gaddr) {
    asm volatile("cp.async.cg.shared.global [%0], [%1], 16;" :: "r"(saddr), "l"(gaddr));
}
#define CP_COMMIT() asm volatile("cp.async.commit_group;" ::: "memory")
#define CP_WAIT(n)  asm volatile("cp.async.wait_group %0;" :: "n"(n) : "memory")

__device__ __forceinline__ void ldsm_x4(uint32_t& r0, uint32_t& r1, uint32_t& r2, uint32_t& r3,
                                        uint32_t addr) {
    asm volatile("ldmatrix.sync.aligned.m8n8.x4.shared.b16 {%0,%1,%2,%3}, [%4];"
        : "=r"(r0), "=r"(r1), "=r"(r2), "=r"(r3) : "r"(addr));
}

__device__ __forceinline__ void mma_f16(float* c, const uint32_t* a,
                                        uint32_t b0, uint32_t b1) {
    asm volatile(
        "mma.sync.aligned.m16n8k16.row.col.f32.f16.f16.f32 "
        "{%0,%1,%2,%3}, {%4,%5,%6,%7}, {%8,%9}, {%0,%1,%2,%3};"
        : "+f"(c[0]), "+f"(c[1]), "+f"(c[2]), "+f"(c[3])
        : "r"(a[0]), "r"(a[1]), "r"(a[2]), "r"(a[3]), "r"(b0), "r"(b1));
}

__device__ __forceinline__ uint32_t packh2(float a, float b) {
    __half h0 = __float2half_rn(a), h1 = __float2half_rn(b);
    return (uint32_t)__half_as_ushort(h0) | ((uint32_t)__half_as_ushort(h1) << 16);
}

#define RSTRIDE 80

// ---------------------------------------------------------------------------
// 128x64 pure-fp16 GEMM tile (R6 pipeline: 2-stage, issue->wait->sync)
//   smem/stage: A[128x32]@0 (10240) + B[64x32]@10240 (5120) = 15360
// ---------------------------------------------------------------------------
#define SS_B  10240
#define SS_STG 15360
#define GEMM_SMEM_SS (2 * SS_STG)   // 30720

__device__ __forceinline__ void gemm_tile_ss(
    const __half* __restrict__ A, int lda,
    const __half* __restrict__ B, int ldb,
    int K, uint32_t sbase, float acc[2][4][4])
{
    const int tid = threadIdx.x;
    const int l = tid & 31;
    const int wid = tid >> 5;
    const int warp_m = wid & 3, warp_n = wid >> 2;
    const int arow = tid >> 2;
    const int q4   = tid & 3;

    const uint32_t a_row = (uint32_t)(warp_m * 32 + (l & 15));
    const uint32_t a_co  = (uint32_t)((l >> 4) << 4);
    const uint32_t b_row = (uint32_t)(warp_n * 32 + (l & 7) + ((l >> 4) & 1) * 8);
    const uint32_t b_co  = (uint32_t)(((l >> 3) & 1) << 4);

    auto issue = [&](int s, int kb) {
        const uint32_t st = sbase + (uint32_t)s * SS_STG;
        #pragma unroll
        for (int j = 0; j < 2; ++j) {
            const int row = arow + j * 64;
            cp16(st + (uint32_t)(row * RSTRIDE + q4 * 16),
                 A + (size_t)row * lda + kb + q4 * 8);
        }
        cp16(st + SS_B + (uint32_t)(arow * RSTRIDE + q4 * 16),
             B + (size_t)arow * ldb + kb + q4 * 8);
    };

    issue(0, 0);
    CP_COMMIT();

    const int KT = K >> 5;
    for (int kt = 0; kt < KT; ++kt) {
        if (kt + 1 < KT) {
            issue((kt + 1) & 1, (kt + 1) << 5);
            CP_COMMIT();
            CP_WAIT(1);
        } else {
            CP_WAIT(0);
        }
        __syncthreads();

        const uint32_t st = sbase + (uint32_t)((kt & 1) * SS_STG);
        #pragma unroll
        for (int ks = 0; ks < 2; ++ks) {
            uint32_t ah[2][4], bh[2][4];
            #pragma unroll
            for (int bm = 0; bm < 2; ++bm) {
                const uint32_t aaddr = st + (a_row + bm * 16) * RSTRIDE + ks * 32 + a_co;
                ldsm_x4(ah[bm][0], ah[bm][1], ah[bm][2], ah[bm][3], aaddr);
            }
            #pragma unroll
            for (int np = 0; np < 2; ++np) {
                const uint32_t baddr = st + SS_B + (b_row + np * 16) * RSTRIDE + ks * 32 + b_co;
                ldsm_x4(bh[np][0], bh[np][1], bh[np][2], bh[np][3], baddr);
            }
            #pragma unroll
            for (int np = 0; np < 2; ++np)
                #pragma unroll
                for (int bm = 0; bm < 2; ++bm) {
                    mma_f16(acc[bm][np * 2],     ah[bm], bh[np][0], bh[np][1]);
                    mma_f16(acc[bm][np * 2 + 1], ah[bm], bh[np][2], bh[np][3]);
                }
        }
        __syncthreads();
    }
}

// ---------------------------------------------------------------------------
// Kernel 0a: weight preconversion (single fp16)
// ---------------------------------------------------------------------------
__global__ __launch_bounds__(256)
void prep_kernel(const float* __restrict__ w1, const float* __restrict__ wf,
                 const float* __restrict__ ws, const float* __restrict__ wg)
{
    const int idx = blockIdx.x * 256 + threadIdx.x;
    const int NW1 = ICH * KCONV;
    if (idx < NW1) {
        g_w1[idx] = __float2half_rn(w1[idx]);
    } else {
        int j = idx - NW1;
        if (j >= 3 * NFC * ICH) return;
        const int which = j >> 15;
        const int e = j & 32767;
        float v = (which == 0 ? wf : which == 1 ? ws : wg)[e];
        __half h = __float2half_rn(v);
        if (which == 0)      g_wf[e] = h;
        else if (which == 1) g_ws[e] = h;
        else                 g_wg[e] = h;
    }
}

// ---------------------------------------------------------------------------
// Kernel 0b: im2col of x into single fp16
// ---------------------------------------------------------------------------
#define I2C_RS 264
#define I2C_SMEM (64 * I2C_RS * 2)

__global__ __launch_bounds__(256, 1)
void im2col_kernel(const float* __restrict__ x)
{
    extern __shared__ char smraw[];
    __half* sh = (__half*)smraw;

    const int bx = blockIdx.x;
    const int icc = bx & 7;
    const int oh  = (bx >> 3) & 31;
    const int b   = bx >> 8;
    const int t = threadIdx.x;

    #pragma unroll
    for (int it = 0; it < 16; ++it) {
        const int f = t + it * 256;
        const int w4 = f & 63;
        const int kh = (f >> 6) & 7;
        const int i  = f >> 9;
        const float4 v = *(const float4*)&x[((size_t)(b * 64 + icc * 8 + i) * 256 + oh * 8 + kh) * 256 + w4 * 4];
        const int row = i * 8 + kh;
        sh[row * I2C_RS + w4 * 4 + 0] = __float2half_rn(v.x);
        sh[row * I2C_RS + w4 * 4 + 1] = __float2half_rn(v.y);
        sh[row * I2C_RS + w4 * 4 + 2] = __float2half_rn(v.z);
        sh[row * I2C_RS + w4 * 4 + 3] = __float2half_rn(v.w);
    }
    __syncthreads();

    #pragma unroll
    for (int it = 0; it < 8; ++it) {
        const int f = t + it * 256;
        const int kh = f & 7;
        const int i  = (f >> 3) & 7;
        const int ow = f >> 6;
        const int row = i * 8 + kh;
        const size_t r = (size_t)b * 1024 + oh * 32 + ow;
        const size_t kbase = (size_t)(icc * 8 + i) * 64 + kh * 8;
        *(uint4*)&g_x[r * KCONV + kbase] = *(const uint4*)&sh[row * I2C_RS + ow * 8];
    }
}

// ---------------------------------------------------------------------------
// Kernel 1: conv1 GEMM (pure fp16); grid (64 m, 4 n)
// ---------------------------------------------------------------------------
__global__ __launch_bounds__(256, 2)
void conv1_mma_kernel(const float* __restrict__ bnS, const float* __restrict__ bnB)
{
    extern __shared__ char smem[];
    const uint32_t sbase = smem_u32(smem);

    const int m0 = blockIdx.x * 128;
    const int n0 = blockIdx.y * 64;

    float acc[2][4][4] = {};
    gemm_tile_ss(g_x + (size_t)m0 * KCONV, KCONV,
                 g_w1 + (size_t)n0 * KCONV, KCONV,
                 KCONV, sbase, acc);

    const int wid = threadIdx.x >> 5, l = threadIdx.x & 31;
    const int erow0 = m0 + (wid & 3) * 32 + (l >> 2);
    const int ecol0 = n0 + (wid >> 2) * 32 + (l & 3) * 2;
    #pragma unroll
    for (int bm = 0; bm < 2; ++bm) {
        #pragma unroll
        for (int nb = 0; nb < 4; ++nb) {
            const int col = ecol0 + nb * 8;
            const float s0 = bnS[col], s1 = bnS[col + 1];
            const float v0 = bnB[col], v1 = bnB[col + 1];
            const int r0 = erow0 + bm * 16;
            float a0 = fmaxf(acc[bm][nb][0] * s0 + v0, 0.0f);
            float a1 = fmaxf(acc[bm][nb][1] * s1 + v1, 0.0f);
            float a2 = fmaxf(acc[bm][nb][2] * s0 + v0, 0.0f);
            float a3 = fmaxf(acc[bm][nb][3] * s1 + v1, 0.0f);
            *(uint32_t*)&g_y[(size_t)r0 * ICH + col] = packh2(a0, a1);
            *(uint32_t*)&g_y[(size_t)(r0 + 8) * ICH + col] = packh2(a2, a3);
        }
    }
}

// ---------------------------------------------------------------------------
// Kernel 2: projections (pure fp16); grid (64 m, 2 n, 3)
// ---------------------------------------------------------------------------
__global__ __launch_bounds__(256, 2)
void proj_mma_kernel(const float* __restrict__ sf, const float* __restrict__ bf,
                     const float* __restrict__ ss, const float* __restrict__ bs,
                     const float* __restrict__ sg, const float* __restrict__ bg)
{
    extern __shared__ char smem[];
    const uint32_t sbase = smem_u32(smem);

    const int z = blockIdx.z;
    const __half* W = (z == 0) ? g_wf : (z == 1) ? g_ws : g_wg;
    const float* Sv = (z == 0) ? sf : (z == 1) ? ss : sg;
    const float* Bv = (z == 0) ? bf : (z == 1) ? bs : bg;

    const int m0 = blockIdx.x * 128;
    const int n0 = blockIdx.y * 64;

    float acc[2][4][4] = {};
    gemm_tile_ss(g_y + (size_t)m0 * ICH, ICH,
                 W + (size_t)n0 * ICH, ICH,
                 ICH, sbase, acc);

    const int wid = threadIdx.x >> 5, l = threadIdx.x & 31;
    const int erow0 = m0 + (wid & 3) * 32 + (l >> 2);
    const int ecol0 = n0 + (wid >> 2) * 32 + (l & 3) * 2;
    #pragma unroll
    for (int bm = 0; bm < 2; ++bm) {
        #pragma unroll
        for (int nb = 0; nb < 4; ++nb) {
            const int col = ecol0 + nb * 8;
            const float s0 = Sv[col], s1 = Sv[col + 1];
            const float v0 = Bv[col], v1 = Bv[col + 1];
            const int r0 = erow0 + bm * 16;
            float a0 = fmaxf(acc[bm][nb][0] * s0 + v0, 0.0f);
            float a1 = fmaxf(acc[bm][nb][1] * s1 + v1, 0.0f);
            float a2 = fmaxf(acc[bm][nb][2] * s0 + v0, 0.0f);
            float a3 = fmaxf(acc[bm][nb][3] * s1 + v1, 0.0f);
            if (z < 2) {
                __half* Oh = (z == 0) ? g_fai : g_sit;
                *(uint32_t*)&Oh[(size_t)r0 * NFC + col] = packh2(a0, a1);
                *(uint32_t*)&Oh[(size_t)(r0 + 8) * NFC + col] = packh2(a2, a3);
            } else {
                const int bb = r0 >> 10;
                const int n  = r0 & 1023;
                const size_t base = (size_t)bb * NFC * NPIX;
                g_gT[base + (size_t)col * NPIX + n]            = __float2half_rn(a0);
                g_gT[base + (size_t)(col + 1) * NPIX + n]      = __float2half_rn(a1);
                g_gT[base + (size_t)col * NPIX + n + 8]        = __float2half_rn(a2);
                g_gT[base + (size_t)(col + 1) * NPIX + n + 8]  = __float2half_rn(a3);
            }
        }
    }
}

// ---------------------------------------------------------------------------
// Kernel 3: score S = sigmoid(fai . sit); grid (8 m, 16 n, 8 b)
// ---------------------------------------------------------------------------
__global__ __launch_bounds__(256, 2)
void score_mma_kernel()
{
    extern __shared__ char smem[];
    const uint32_t sbase = smem_u32(smem);

    const int b  = blockIdx.z;
    const int m0 = blockIdx.x * 128;
    const int n0 = blockIdx.y * 64;
    const size_t abase = (size_t)b * NPIX * NFC;

    float acc[2][4][4] = {};
    gemm_tile_ss(g_fai + abase + (size_t)m0 * NFC, NFC,
                 g_sit + abase + (size_t)n0 * NFC, NFC,
                 NFC, sbase, acc);

    const size_t sb_out = (size_t)b * NPIX * NPIX;
    const int wid = threadIdx.x >> 5, l = threadIdx.x & 31;
    const int erow0 = m0 + (wid & 3) * 32 + (l >> 2);
    const int ecol0 = n0 + (wid >> 2) * 32 + (l & 3) * 2;
    #pragma unroll
    for (int bm = 0; bm < 2; ++bm) {
        #pragma unroll
        for (int nb = 0; nb < 4; ++nb) {
            const int col = ecol0 + nb * 8;
            const int r0 = erow0 + bm * 16;
            float a0 = 1.0f / (1.0f + expf(-acc[bm][nb][0]));
            float a1 = 1.0f / (1.0f + expf(-acc[bm][nb][1]));
            float a2 = 1.0f / (1.0f + expf(-acc[bm][nb][2]));
            float a3 = 1.0f / (1.0f + expf(-acc[bm][nb][3]));
            *(uint32_t*)&g_S[sb_out + (size_t)r0 * NPIX + col] = packh2(a0, a1);
            *(uint32_t*)&g_S[sb_out + (size_t)(r0 + 8) * NPIX + col] = packh2(a2, a3);
        }
    }
}

// ---------------------------------------------------------------------------
// Kernel 4: att = S @ gamaT, split-K(2); grid (8 m, 2 n, 16)
// ---------------------------------------------------------------------------
__global__ __launch_bounds__(256, 2)
void attn_mma_kernel()
{
    extern __shared__ char smem[];
    const uint32_t sbase = smem_u32(smem);

    const int z  = blockIdx.z;
    const int b  = z >> 1;
    const int ks = z & 1;
    const int m0 = blockIdx.x * 128;
    const int n0 = blockIdx.y * 64;
    const size_t sBase = (size_t)b * NPIX * NPIX;
    const size_t gBase = (size_t)b * NFC * NPIX;
    const int kofs = ks * 512;

    float acc[2][4][4] = {};
    gemm_tile_ss(g_S + sBase + (size_t)m0 * NPIX + kofs, NPIX,
                 g_gT + gBase + (size_t)n0 * NPIX + kofs, NPIX,
                 512, sbase, acc);

    float* outp = ks ? g_att1 : g_att0;
    const int wid = threadIdx.x >> 5, l = threadIdx.x & 31;
    const int erow0 = m0 + (wid & 3) * 32 + (l >> 2);
    const int ecol0 = n0 + (wid >> 2) * 32 + (l & 3) * 2;
    #pragma unroll
    for (int bm = 0; bm < 2; ++bm) {
        #pragma unroll
        for (int nb = 0; nb < 4; ++nb) {
            const int col = ecol0 + nb * 8;
            const int r0 = erow0 + bm * 16;
            float2 o0 = {acc[bm][nb][0], acc[bm][nb][1]};
            float2 o1 = {acc[bm][nb][2], acc[bm][nb][3]};
            *(float2*)&outp[((size_t)b * NPIX + r0) * NFC + col] = o0;
            *(float2*)&outp[((size_t)b * NPIX + r0 + 8) * NFC + col] = o1;
        }
    }
}

// ---------------------------------------------------------------------------
// Kernel 5: bilinear upsample x8 (align_corners), sums split-K partials
// ---------------------------------------------------------------------------
__global__ __launch_bounds__(256)
void upsample_kernel(float* __restrict__ out)
{
    __shared__ float rows[3][32];
    const int gx = blockIdx.x;
    const int yt = gx & 31;
    const int c  = (gx >> 5) & 127;
    const int b  = gx >> 12;
    const int t = threadIdx.x;

    const float sc = 31.0f / 255.0f;
    const int rbase = (int)floorf((float)(yt * 8) * sc);
    if (t < 96) {
        const int rr = t >> 5, xx = t & 31;
        const int r = min(rbase + rr, 31);
        const size_t idx = ((size_t)b * NPIX + r * 32 + xx) * NFC + c;
        rows[rr][xx] = g_att0[idx] + g_att1[idx];
    }
    __syncthreads();

    const int xo = t;
    const float xs = (float)xo * sc;
    const int x0 = (int)floorf(xs);
    const float wx = xs - (float)x0;
    const int x1 = min(x0 + 1, 31);
    const size_t obase = ((size_t)(b * 128 + c)) * 256 * 256;

    #pragma unroll
    for (int i = 0; i < 8; ++i) {
        const int yo = yt * 8 + i;
        const float ysf = (float)yo * sc;
        const int y0 = (int)floorf(ysf);
        const float wy = ysf - (float)y0;
        const int y1 = min(y0 + 1, 31);
        const int r0 = y0 - rbase, r1 = y1 - rbase;
        const float v00 = rows[r0][x0], v01 = rows[r0][x1];
        const float v10 = rows[r1][x0], v11 = rows[r1][x1];
        const float top0 = v00 * (1.0f - wy) + v10 * wy;
        const float top1 = v01 * (1.0f - wy) + v11 * wy;
        out[obase + (size_t)yo * 256 + xo] = top0 * (1.0f - wx) + top1 * wx;
    }
}

// ---------------------------------------------------------------------------
// Launch
// ---------------------------------------------------------------------------
extern "C" void kernel_launch(void* const* d_in, const int* in_sizes, int n_in,
                              void* d_out, int out_size)
{
    const float* x     = (const float*)d_in[0];
    const float* w1    = (const float*)d_in[1];
    const float* bn1_s = (const float*)d_in[2];
    const float* bn1_b = (const float*)d_in[3];
    const float* w_fai = (const float*)d_in[4];
    const float* bnf_s = (const float*)d_in[5];
    const float* bnf_b = (const float*)d_in[6];
    const float* w_sit = (const float*)d_in[7];
    const float* bns_s = (const float*)d_in[8];
    const float* bns_b = (const float*)d_in[9];
    const float* w_gam = (const float*)d_in[10];
    const float* bng_s = (const float*)d_in[11];
    const float* bng_b = (const float*)d_in[12];
    float* out = (float*)d_out;

    static bool attr_done = false;
    if (!attr_done) {
        cudaFuncSetAttribute(conv1_mma_kernel, cudaFuncAttributeMaxDynamicSharedMemorySize, GEMM_SMEM_SS);
        cudaFuncSetAttribute(proj_mma_kernel,  cudaFuncAttributeMaxDynamicSharedMemorySize, GEMM_SMEM_SS);
        cudaFuncSetAttribute(score_mma_kernel, cudaFuncAttributeMaxDynamicSharedMemorySize, GEMM_SMEM_SS);
        cudaFuncSetAttribute(attn_mma_kernel,  cudaFuncAttributeMaxDynamicSharedMemorySize, GEMM_SMEM_SS);
        cudaFuncSetAttribute(im2col_kernel,    cudaFuncAttributeMaxDynamicSharedMemorySize, I2C_SMEM);
        attr_done = true;
    }

    // 0a. weight preconversion (single fp16)
    {
        const int total = ICH * KCONV + 3 * NFC * ICH;
        prep_kernel<<<(total + 255) / 256, 256>>>(w1, w_fai, w_sit, w_gam);
    }
    // 0b. im2col(x) -> single fp16
    im2col_kernel<<<2048, 256, I2C_SMEM>>>(x);
    // 1. conv1 GEMM + BN + ReLU (pure fp16)
    {
        dim3 grid(MROWS / 128, ICH / 64);
        conv1_mma_kernel<<<grid, 256, GEMM_SMEM_SS>>>(bn1_s, bn1_b);
    }
    // 2. projections (pure fp16)
    {
        dim3 grid(MROWS / 128, NFC / 64, 3);
        proj_mma_kernel<<<grid, 256, GEMM_SMEM_SS>>>(bnf_s, bnf_b, bns_s, bns_b, bng_s, bng_b);
    }
    // 3. S = sigmoid(fai . sit)
    {
        dim3 grid(NPIX / 128, NPIX / 64, BATCH);
        score_mma_kernel<<<grid, 256, GEMM_SMEM_SS>>>();
    }
    // 4. att = S @ gamaT (split-K 2)
    {
        dim3 grid(NPIX / 128, NFC / 64, BATCH * 2);
        attn_mma_kernel<<<grid, 256, GEMM_SMEM_SS>>>();
    }
    // 5. upsample (+ split-K reduce)
    upsample_kernel<<<BATCH * 128 * 32, 256>>>(out);
}